// round 12
// baseline (speedup 1.0000x reference)
#include <cuda_runtime.h>
#include <cuda_bf16.h>
#include <cuda_fp16.h>
#include <math.h>
#include <stdint.h>

// ---------------------------------------------------------------------------
// Mamba forward, L=2048, 4 layers.
// Big GEMMs via mma.sync (HMMA fp16), CTA 128x128, BK=64, 3-stage cp.async,
// 2 CTAs/SM: layer GEMMs = fp16 activation-hi/lo 2-pass, lm head = 1-pass.
// Small GEMMs + scan (gate fused) + elementwise in fp32 SIMT;
// softplus fused into dt GEMM epilogue.
// ---------------------------------------------------------------------------

#define LSEQ    2048
#define NEMBD   1024
#define DINNER  2048
#define DSTATE  16
#define DTRANK  64
#define DCONV   4
#define NVOCAB  50257
#define NLAYERS 4
#define XDBL_W  (DTRANK + 2 * DSTATE)   // 96

// ----------------------------- scratch (static) ----------------------------
__device__ __align__(16) float g_x    [LSEQ * NEMBD];
__device__ __align__(16) float g_xr   [LSEQ * 2 * DINNER];
__device__ __align__(16) float g_u    [LSEQ * DINNER];
__device__ __align__(16) float g_xdbl [LSEQ * XDBL_W];
__device__ __align__(16) float g_delta[LSEQ * DINNER];
__device__ __align__(16) float g_part [8 * LSEQ * XDBL_W];

__device__ __align__(16) __half g_hh [LSEQ * NEMBD];    // activations hi
__device__ __align__(16) __half g_hl [LSEQ * NEMBD];    // activations lo
__device__ __align__(16) __half g_yh [LSEQ * DINNER];
__device__ __align__(16) __half g_yl [LSEQ * DINNER];
__device__ __align__(16) __half g_wi [NLAYERS * 2 * DINNER * NEMBD];
__device__ __align__(16) __half g_wo [NLAYERS * NEMBD * DINNER];
__device__ __align__(16) __half g_embh[(size_t)NVOCAB * NEMBD];

// ----------------------------- MMA helpers ---------------------------------
__device__ __forceinline__ void ldm_x4(uint32_t* r, uint32_t a) {
    asm volatile("ldmatrix.sync.aligned.m8n8.x4.shared.b16 {%0,%1,%2,%3}, [%4];"
                 : "=r"(r[0]), "=r"(r[1]), "=r"(r[2]), "=r"(r[3]) : "r"(a));
}
__device__ __forceinline__ void mma_16816(float* c, const uint32_t* a, const uint32_t* b) {
    asm volatile("mma.sync.aligned.m16n8k16.row.col.f32.f16.f16.f32 "
        "{%0,%1,%2,%3}, {%4,%5,%6,%7}, {%8,%9}, {%0,%1,%2,%3};"
        : "+f"(c[0]), "+f"(c[1]), "+f"(c[2]), "+f"(c[3])
        : "r"(a[0]), "r"(a[1]), "r"(a[2]), "r"(a[3]), "r"(b[0]), "r"(b[1]));
}

#define CPASYNC16(dst, src, sz) \
    asm volatile("cp.async.cg.shared.global [%0], [%1], 16, %2;" \
                 :: "r"(dst), "l"(src), "r"(sz))

// ------------- HMMA NT GEMM: C[M,N] (+)= sum_p A_p B^T ---------------------
// CTA 128x128, BK=64, 3-stage cp.async, 8 warps (2Mx4N), warp tile 64x32,
// 2 CTAs/SM (smem 110.6KB). A,B fp16 K-major; M%128==0, K%64==0, N guarded.
// (R8 config — benched 2974us; do not grow the COMPUTE body: reg budget 128.)
template <bool ACC>
__global__ __launch_bounds__(256, 2) void gemm_mma4(
    const uint16_t* __restrict__ A0, const uint16_t* __restrict__ A1,
    const uint16_t* __restrict__ B,
    int npass, float* __restrict__ C, int N, int K, int ldc) {
    extern __shared__ __align__(16) uint16_t sm[];
    constexpr int PITCH = 72;                // 64 halfs + 8 pad (144B rows)
    constexpr int ASTR = 128 * PITCH;
    constexpr int BSTR = 128 * PITCH;

    const int tid = threadIdx.x, lane = tid & 31, wid = tid >> 5;
    const int bm = blockIdx.x * 128, bn = blockIdx.y * 128;
    const int kc64 = K >> 6;
    const int NC = npass * kc64;

    const uint32_t smBase = (uint32_t)__cvta_generic_to_shared(sm);
    const int lrow = tid >> 3, lch = tid & 7;

    const int arow = (lane & 7) + ((lane >> 3) & 1) * 8;
    const int akc  = lane >> 4;
    const int brow = (lane & 7) + ((lane >> 4) << 3);
    const int bkc  = (lane >> 3) & 1;
    const int wm = (wid & 1) * 64;
    const int wn = (wid >> 1) * 32;

    float acc[4][4][4];
    #pragma unroll
    for (int i = 0; i < 4; i++)
        #pragma unroll
        for (int j = 0; j < 4; j++)
            #pragma unroll
            for (int k = 0; k < 4; k++) acc[i][j][k] = 0.f;

#define ISSUE(st, c) do { \
    int _p = (c) / kc64, _k = (c) - _p * kc64; \
    const uint16_t* _Aw = (_p == 0) ? A0 : A1; \
    _Pragma("unroll") \
    for (int _it = 0; _it < 4; _it++) { \
        int _r = lrow + _it * 32; \
        const uint16_t* _ga = _Aw + (size_t)(bm + _r) * K + _k * 64 + lch * 8; \
        uint32_t _da = smBase + 2u * ((st) * ASTR + _r * PITCH + lch * 8); \
        CPASYNC16(_da, _ga, 16); \
    } \
    _Pragma("unroll") \
    for (int _it = 0; _it < 4; _it++) { \
        int _r = lrow + _it * 32; \
        int _gr = bn + _r; \
        const uint16_t* _gb = B + (size_t)((_gr < N) ? _gr : 0) * K + _k * 64 + lch * 8; \
        uint32_t _db = smBase + 2u * (3 * ASTR + (st) * BSTR + _r * PITCH + lch * 8); \
        CPASYNC16(_db, _gb, (_gr < N) ? 16 : 0); \
    } \
  } while (0)

#define COMPUTE(st) do { \
    uint32_t _ab = smBase + 2u * ((st) * ASTR); \
    uint32_t _bb = smBase + 2u * (3 * ASTR + (st) * BSTR); \
    _Pragma("unroll") \
    for (int kk = 0; kk < 4; kk++) { \
        uint32_t af[4][4], bf[2][4]; \
        _Pragma("unroll") \
        for (int mi = 0; mi < 4; mi++) \
            ldm_x4(af[mi], _ab + 2u * ((wm + mi * 16 + arow) * PITCH + (kk * 2 + akc) * 8)); \
        _Pragma("unroll") \
        for (int nb = 0; nb < 2; nb++) \
            ldm_x4(bf[nb], _bb + 2u * ((wn + nb * 16 + brow) * PITCH + (kk * 2 + bkc) * 8)); \
        _Pragma("unroll") \
        for (int mi = 0; mi < 4; mi++) \
            _Pragma("unroll") \
            for (int ni = 0; ni < 4; ni++) \
                mma_16816(acc[mi][ni], af[mi], &bf[ni >> 1][(ni & 1) * 2]); \
    } \
  } while (0)

    ISSUE(0, 0);
    asm volatile("cp.async.commit_group;" ::: "memory");
    ISSUE(1, 1);
    asm volatile("cp.async.commit_group;" ::: "memory");

    for (int c = 0; c < NC; c++) {
        asm volatile("cp.async.wait_group 1;" ::: "memory");
        __syncthreads();
        if (c + 2 < NC) ISSUE((c + 2) % 3, c + 2);
        asm volatile("cp.async.commit_group;" ::: "memory");
        COMPUTE(c % 3);
    }
#undef ISSUE
#undef COMPUTE

    // epilogue
    const int gid = lane >> 2, q2 = (lane & 3) * 2;
    #pragma unroll
    for (int mi = 0; mi < 4; mi++) {
        const size_t row0 = (size_t)(bm + wm + mi * 16 + gid);
        const size_t row1 = row0 + 8;
        #pragma unroll
        for (int ni = 0; ni < 4; ni++) {
            const int col = bn + wn + ni * 8 + q2;
            const float* cf = acc[mi][ni];
            if (col < N) {
                if (ACC) { C[row0 * ldc + col] += cf[0]; C[row1 * ldc + col] += cf[2]; }
                else     { C[row0 * ldc + col]  = cf[0]; C[row1 * ldc + col]  = cf[2]; }
            }
            if (col + 1 < N) {
                if (ACC) { C[row0 * ldc + col + 1] += cf[1]; C[row1 * ldc + col + 1] += cf[3]; }
                else     { C[row0 * ldc + col + 1]  = cf[1]; C[row1 * ldc + col + 1]  = cf[3]; }
            }
        }
    }
}

#define SMEM_G (3 * (128 + 128) * 72 * 2)   // 110592 B

// ----------------------------- small helpers -------------------------------
__device__ __forceinline__ float sigm(float x) { return 1.0f / (1.0f + expf(-x)); }
__device__ __forceinline__ uint32_t packh2(float a, float b) {
    return (uint32_t)__half_as_ushort(__float2half_rn(a)) |
           ((uint32_t)__half_as_ushort(__float2half_rn(b)) << 16);
}
__device__ __forceinline__ void split2h(float a, float b, uint32_t& hi, uint32_t& lo) {
    __half ha = __float2half_rn(a), hb = __float2half_rn(b);
    float la = a - __half2float(ha), lb = b - __half2float(hb);
    hi = (uint32_t)__half_as_ushort(ha) | ((uint32_t)__half_as_ushort(hb) << 16);
    lo = packh2(la, lb);
}

// ----------------------------- conversions ---------------------------------
__global__ void convert_half_kernel(const float* __restrict__ src,
                                    __half* __restrict__ dst, int n4) {
    int i = blockIdx.x * blockDim.x + threadIdx.x;
    if (i >= n4) return;
    float4 v = reinterpret_cast<const float4*>(src)[i];
    uint2 o;
    o.x = packh2(v.x, v.y);
    o.y = packh2(v.z, v.w);
    reinterpret_cast<uint2*>(dst)[i] = o;
}

// ----------------------------- embedding gather ----------------------------
__global__ void embed_kernel(const int* __restrict__ tokens,
                             const float* __restrict__ emb,
                             float* __restrict__ x) {
    int l = blockIdx.x;
    int tok = tokens[l];
    const float4* src = reinterpret_cast<const float4*>(emb + (size_t)tok * NEMBD);
    float4* dst = reinterpret_cast<float4*>(x + (size_t)l * NEMBD);
    dst[threadIdx.x] = src[threadIdx.x];
}

// ---------------- rmsnorm (width 1024) with fp16 outputs -------------------
template <int OUT_MODE>   // 0: fp16 hi/lo; 1: fp16 single
__global__ void rmsnorm_out_kernel(const float* __restrict__ x,
                                   const float* __restrict__ w,
                                   const float* __restrict__ b,
                                   void* __restrict__ out_hi,
                                   void* __restrict__ out_lo) {
    int l = blockIdx.x;
    const float4* xr = reinterpret_cast<const float4*>(x + (size_t)l * NEMBD);
    float4 v = xr[threadIdx.x];
    float ss = v.x * v.x + v.y * v.y + v.z * v.z + v.w * v.w;
    #pragma unroll
    for (int o = 16; o > 0; o >>= 1) ss += __shfl_xor_sync(0xffffffffu, ss, o);
    __shared__ float wsum[8];
    __shared__ float inv_s;
    if ((threadIdx.x & 31) == 0) wsum[threadIdx.x >> 5] = ss;
    __syncthreads();
    if (threadIdx.x == 0) {
        float t = 0.f;
        #pragma unroll
        for (int k = 0; k < 8; k++) t += wsum[k];
        inv_s = rsqrtf(t / (float)NEMBD + 1e-6f);
    }
    __syncthreads();
    float inv = inv_s;
    float4 wv = reinterpret_cast<const float4*>(w)[threadIdx.x];
    float4 bv = reinterpret_cast<const float4*>(b)[threadIdx.x];
    float o0 = v.x * inv * wv.x + bv.x;
    float o1 = v.y * inv * wv.y + bv.y;
    float o2 = v.z * inv * wv.z + bv.z;
    float o3 = v.w * inv * wv.w + bv.w;
    size_t base = (size_t)l * NEMBD / 4 + threadIdx.x;
    if (OUT_MODE == 0) {
        uint2 h, lo;
        split2h(o0, o1, h.x, lo.x);
        split2h(o2, o3, h.y, lo.y);
        reinterpret_cast<uint2*>(out_hi)[base] = h;
        reinterpret_cast<uint2*>(out_lo)[base] = lo;
    } else {
        uint2 o;
        o.x = packh2(o0, o1);
        o.y = packh2(o2, o3);
        reinterpret_cast<uint2*>(out_hi)[base] = o;
    }
}

// ------------------- fp32 tiled NT GEMM (small GEMMs) ----------------------
// SOFTP: epilogue computes softplus(acc + bias[col]) (dt-proj fusion).
template <bool ACC, bool SPLIT, bool SOFTP>
__global__ __launch_bounds__(256) void gemm_nt(
    const float* __restrict__ A, const float* __restrict__ B,
    float* __restrict__ C, int M, int N, int K,
    int lda, int ldb, int ldc, int kchunk, long long cstride,
    const float* __restrict__ bias) {
    __shared__ float As[16][128 + 4];
    __shared__ float Bs[16][128 + 4];

    int k_begin = 0, k_end = K;
    if (SPLIT) {
        k_begin = blockIdx.z * kchunk;
        k_end = min(K, k_begin + kchunk);
        C += (long long)blockIdx.z * cstride;
    }
    const int bm = blockIdx.y * 128;
    const int bn = blockIdx.x * 128;
    const int tid = threadIdx.x;
    const int tx = tid & 15;
    const int ty = tid >> 4;

    float acc[8][8];
    #pragma unroll
    for (int i = 0; i < 8; i++)
        #pragma unroll
        for (int j = 0; j < 8; j++) acc[i][j] = 0.f;

    for (int k0 = k_begin; k0 < k_end; k0 += 16) {
        #pragma unroll
        for (int s = 0; s < 2; ++s) {
            int idx = tid + s * 256;
            int row = idx >> 2;
            int k4 = (idx & 3) * 4;
            float4 va = *reinterpret_cast<const float4*>(
                &A[(size_t)(bm + row) * lda + k0 + k4]);
            As[k4 + 0][row] = va.x; As[k4 + 1][row] = va.y;
            As[k4 + 2][row] = va.z; As[k4 + 3][row] = va.w;
            float4 vb;
            if (bn + row < N)
                vb = *reinterpret_cast<const float4*>(
                    &B[(size_t)(bn + row) * ldb + k0 + k4]);
            else
                vb = make_float4(0.f, 0.f, 0.f, 0.f);
            Bs[k4 + 0][row] = vb.x; Bs[k4 + 1][row] = vb.y;
            Bs[k4 + 2][row] = vb.z; Bs[k4 + 3][row] = vb.w;
        }
        __syncthreads();
        #pragma unroll
        for (int kk = 0; kk < 16; ++kk) {
            float a[8], b[8];
            *reinterpret_cast<float4*>(&a[0]) =
                *reinterpret_cast<const float4*>(&As[kk][ty * 4]);
            *reinterpret_cast<float4*>(&a[4]) =
                *reinterpret_cast<const float4*>(&As[kk][64 + ty * 4]);
            *reinterpret_cast<float4*>(&b[0]) =
                *reinterpret_cast<const float4*>(&Bs[kk][tx * 4]);
            *reinterpret_cast<float4*>(&b[4]) =
                *reinterpret_cast<const float4*>(&Bs[kk][64 + tx * 4]);
            #pragma unroll
            for (int i = 0; i < 8; i++)
                #pragma unroll
                for (int j = 0; j < 8; j++)
                    acc[i][j] = fmaf(a[i], b[j], acc[i][j]);
        }
        __syncthreads();
    }

    #pragma unroll
    for (int i = 0; i < 8; i++) {
        int ri = bm + ((i < 4) ? (ty * 4 + i) : (64 + ty * 4 + (i - 4)));
        #pragma unroll
        for (int j = 0; j < 8; j++) {
            int cj = bn + ((j < 4) ? (tx * 4 + j) : (64 + tx * 4 + (j - 4)));
            if (cj < N) {
                size_t off = (size_t)ri * ldc + cj;
                float v = acc[i][j];
                if (SOFTP) {
                    float t = v + bias[cj];
                    v = fmaxf(t, 0.f) + log1pf(expf(-fabsf(t)));
                }
                if (ACC) C[off] += v;
                else     C[off]  = v;
            }
        }
    }
}

__global__ void reduce_split_kernel(const float* __restrict__ part,
                                    float* __restrict__ out,
                                    int n, int nz, long long stride) {
    int i = blockIdx.x * blockDim.x + threadIdx.x;
    if (i < n) {
        float s = 0.f;
        for (int z = 0; z < nz; z++) s += part[(long long)z * stride + i];
        out[i] = s;
    }
}

// --------------------- depthwise causal conv + silu ------------------------
__global__ void conv_silu_kernel(const float* __restrict__ xr,
                                 const float* __restrict__ W,
                                 const float* __restrict__ b,
                                 float* __restrict__ u) {
    int idx = blockIdx.x * blockDim.x + threadIdx.x;
    int d = idx & (DINNER - 1);
    int l = idx >> 11;
    float acc = b[d];
    #pragma unroll
    for (int j = 0; j < DCONV; j++) {
        int t = l - (DCONV - 1) + j;
        if (t >= 0) acc = fmaf(xr[(size_t)t * (2 * DINNER) + d], W[d * DCONV + j], acc);
    }
    u[(size_t)l * DINNER + d] = acc * sigm(acc);
}

// --------------- selective scan with fused silu-gate + split ---------------
#define TCHUNK 64
__global__ __launch_bounds__(256) void scan_kernel(
    const float* __restrict__ delta, const float* __restrict__ u,
    const float* __restrict__ xdbl, const float* __restrict__ xr,
    const float* __restrict__ A_log, const float* __restrict__ Dp,
    __half* __restrict__ yh, __half* __restrict__ yl) {
    const int lane_n = threadIdx.x & 15;
    const int ch_loc = threadIdx.x >> 4;
    const int d = blockIdx.x * 16 + ch_loc;
    const float Aneg = -expf(A_log[(size_t)d * DSTATE + lane_n]);
    const float Dval = Dp[d];
    float s = 0.f;

    __shared__ float Bsh[TCHUNK][16];
    __shared__ float Csh[TCHUNK][16];
    __shared__ float dsh[TCHUNK][16];
    __shared__ float ush[TCHUNK][16];

    for (int t0 = 0; t0 < LSEQ; t0 += TCHUNK) {
        __syncthreads();
        for (int i = threadIdx.x; i < TCHUNK * 16; i += 256) {
            int tt = i >> 4, n = i & 15;
            size_t trow = (size_t)(t0 + tt);
            Bsh[tt][n] = xdbl[trow * XDBL_W + DTRANK + n];
            Csh[tt][n] = xdbl[trow * XDBL_W + DTRANK + DSTATE + n];
            dsh[tt][n] = delta[trow * DINNER + blockIdx.x * 16 + n];
            ush[tt][n] = u    [trow * DINNER + blockIdx.x * 16 + n];
        }
        __syncthreads();
        #pragma unroll 4
        for (int tt = 0; tt < TCHUNK; ++tt) {
            float dt = dsh[tt][ch_loc];
            float uu = ush[tt][ch_loc];
            float dA = __expf(dt * Aneg);
            float dBu = dt * uu * Bsh[tt][lane_n];
            s = fmaf(dA, s, dBu);
            float yv = s * Csh[tt][lane_n];
            yv += __shfl_xor_sync(0xffffffffu, yv, 8);
            yv += __shfl_xor_sync(0xffffffffu, yv, 4);
            yv += __shfl_xor_sync(0xffffffffu, yv, 2);
            yv += __shfl_xor_sync(0xffffffffu, yv, 1);
            if (lane_n == 0) {
                size_t trow = (size_t)(t0 + tt);
                float g = yv + Dval * uu;
                float r = xr[trow * (2 * DINNER) + DINNER + d];
                g *= r * sigm(r);
                __half gh = __float2half_rn(g);
                yh[trow * DINNER + d] = gh;
                yl[trow * DINNER + d] = __float2half_rn(g - __half2float(gh));
            }
        }
    }
}

// ------------------------------- launcher ----------------------------------
extern "C" void kernel_launch(void* const* d_in, const int* in_sizes, int n_in,
                              void* d_out, int out_size) {
    const int*   tokens    = (const int*)  d_in[0];
    const float* emb_W     = (const float*)d_in[1];
    const float* in_proj_W = (const float*)d_in[2];
    const float* conv_W    = (const float*)d_in[3];
    const float* conv_b    = (const float*)d_in[4];
    const float* xproj_W   = (const float*)d_in[5];
    const float* dt_W      = (const float*)d_in[6];
    const float* dt_b      = (const float*)d_in[7];
    const float* A_log     = (const float*)d_in[8];
    const float* Dp        = (const float*)d_in[9];
    const float* out_W     = (const float*)d_in[10];
    const float* rms_w     = (const float*)d_in[11];
    const float* rms_b     = (const float*)d_in[12];
    const float* normf_w   = (const float*)d_in[13];
    const float* normf_b   = (const float*)d_in[14];
    float* out = (float*)d_out;

    float *px, *pxr, *pu, *pxdbl, *pdelta, *ppart;
    __half *phh, *phl, *pyh, *pyl, *pwi, *pwo, *pembh;
    cudaGetSymbolAddress((void**)&px,     g_x);
    cudaGetSymbolAddress((void**)&pxr,    g_xr);
    cudaGetSymbolAddress((void**)&pu,     g_u);
    cudaGetSymbolAddress((void**)&pxdbl,  g_xdbl);
    cudaGetSymbolAddress((void**)&pdelta, g_delta);
    cudaGetSymbolAddress((void**)&ppart,  g_part);
    cudaGetSymbolAddress((void**)&phh,    g_hh);
    cudaGetSymbolAddress((void**)&phl,    g_hl);
    cudaGetSymbolAddress((void**)&pyh,    g_yh);
    cudaGetSymbolAddress((void**)&pyl,    g_yl);
    cudaGetSymbolAddress((void**)&pwi,    g_wi);
    cudaGetSymbolAddress((void**)&pwo,    g_wo);
    cudaGetSymbolAddress((void**)&pembh,  g_embh);

    cudaFuncSetAttribute(gemm_mma4<false>,
        cudaFuncAttributeMaxDynamicSharedMemorySize, SMEM_G);
    cudaFuncSetAttribute(gemm_mma4<true>,
        cudaFuncAttributeMaxDynamicSharedMemorySize, SMEM_G);

    // ---- weight conversions to fp16 (every launch; deterministic) ----
    {
        int n4 = NLAYERS * 2 * DINNER * NEMBD / 4;
        convert_half_kernel<<<(n4 + 255) / 256, 256>>>(in_proj_W, pwi, n4);
        n4 = NLAYERS * NEMBD * DINNER / 4;
        convert_half_kernel<<<(n4 + 255) / 256, 256>>>(out_W, pwo, n4);
        n4 = (int)((size_t)NVOCAB * NEMBD / 4);
        convert_half_kernel<<<(n4 + 255) / 256, 256>>>(emb_W, pembh, n4);
    }

    embed_kernel<<<LSEQ, 256>>>(tokens, emb_W, px);

    for (int i = 0; i < NLAYERS; i++) {
        rmsnorm_out_kernel<0><<<LSEQ, 256>>>(px, rms_w + i * NEMBD,
                                             rms_b + i * NEMBD, phh, phl);

        // in_proj: xr[L,4096] = h @ W^T  (fp16 hi/lo 2-pass)
        {
            const uint16_t* bw = (const uint16_t*)(pwi + (size_t)i * 2 * DINNER * NEMBD);
            dim3 g(LSEQ / 128, 2 * DINNER / 128);
            gemm_mma4<false><<<g, 256, SMEM_G>>>(
                (const uint16_t*)phh, (const uint16_t*)phl, bw,
                2, pxr, 2 * DINNER, NEMBD, 2 * DINNER);
        }

        conv_silu_kernel<<<LSEQ * DINNER / 256, 256>>>(
            pxr, conv_W + (size_t)i * DINNER * DCONV, conv_b + i * DINNER, pu);

        // x_proj (N=96): split-K fp32
        {
            dim3 grid(1, LSEQ / 128, 8);
            gemm_nt<false, true, false><<<grid, 256>>>(
                pu, xproj_W + (size_t)i * XDBL_W * DINNER, ppart,
                LSEQ, XDBL_W, DINNER, DINNER, DINNER, XDBL_W,
                DINNER / 8, (long long)LSEQ * XDBL_W, nullptr);
            int n = LSEQ * XDBL_W;
            reduce_split_kernel<<<(n + 255) / 256, 256>>>(
                ppart, pxdbl, n, 8, (long long)LSEQ * XDBL_W);
        }

        // dt proj + fused softplus
        {
            dim3 grid(DINNER / 128, LSEQ / 128);
            gemm_nt<false, false, true><<<grid, 256>>>(
                pxdbl, dt_W + (size_t)i * DINNER * DTRANK, pdelta,
                LSEQ, DINNER, DTRANK, XDBL_W, DTRANK, DINNER, 0, 0,
                dt_b + i * DINNER);
        }

        // scan + fused gate + fp16 split
        scan_kernel<<<DINNER / 16, 256>>>(
            pdelta, pu, pxdbl, pxr,
            A_log + (size_t)i * DINNER * DSTATE, Dp + i * DINNER, pyh, pyl);

        // out_proj accumulate: x += y @ out_W^T  (fp16 hi/lo 2-pass)
        {
            const uint16_t* bw = (const uint16_t*)(pwo + (size_t)i * NEMBD * DINNER);
            dim3 g(LSEQ / 128, NEMBD / 128);
            gemm_mma4<true><<<g, 256, SMEM_G>>>(
                (const uint16_t*)pyh, (const uint16_t*)pyl, bw,
                2, px, NEMBD, DINNER, NEMBD);
        }
    }

    // final norm (fp16 out) + tied lm head (fp16 single pass)
    rmsnorm_out_kernel<1><<<LSEQ, 256>>>(px, normf_w, normf_b, phh, nullptr);
    {
        dim3 g(LSEQ / 128, (NVOCAB + 127) / 128);
        const uint16_t* ah = (const uint16_t*)phh;
        const uint16_t* bh = (const uint16_t*)pembh;
        gemm_mma4<false><<<g, 256, SMEM_G>>>(
            ah, ah, bh, 1, out, NVOCAB, NEMBD, NVOCAB);
    }
}

// round 13
// speedup vs baseline: 1.8386x; 1.8386x over previous
#include <cuda_runtime.h>
#include <cuda_bf16.h>
#include <cuda_fp16.h>
#include <math.h>
#include <stdint.h>

// ---------------------------------------------------------------------------
// Mamba forward, L=2048, 4 layers.
// Big GEMMs via mma.sync (HMMA fp16), CTA 128x128, BK=64, 3-stage cp.async,
// 2 CTAs/SM: layer GEMMs = fp16 activation-hi/lo 2-pass, lm head = 1-pass.
// Small GEMMs + scan (gate fused, residual STAGED via smem) + fp32 SIMT;
// softplus fused into dt GEMM epilogue.
// ---------------------------------------------------------------------------

#define LSEQ    2048
#define NEMBD   1024
#define DINNER  2048
#define DSTATE  16
#define DTRANK  64
#define DCONV   4
#define NVOCAB  50257
#define NLAYERS 4
#define XDBL_W  (DTRANK + 2 * DSTATE)   // 96

// ----------------------------- scratch (static) ----------------------------
__device__ __align__(16) float g_x    [LSEQ * NEMBD];
__device__ __align__(16) float g_xr   [LSEQ * 2 * DINNER];
__device__ __align__(16) float g_u    [LSEQ * DINNER];
__device__ __align__(16) float g_xdbl [LSEQ * XDBL_W];
__device__ __align__(16) float g_delta[LSEQ * DINNER];
__device__ __align__(16) float g_part [8 * LSEQ * XDBL_W];

__device__ __align__(16) __half g_hh [LSEQ * NEMBD];    // activations hi
__device__ __align__(16) __half g_hl [LSEQ * NEMBD];    // activations lo
__device__ __align__(16) __half g_yh [LSEQ * DINNER];
__device__ __align__(16) __half g_yl [LSEQ * DINNER];
__device__ __align__(16) __half g_wi [NLAYERS * 2 * DINNER * NEMBD];
__device__ __align__(16) __half g_wo [NLAYERS * NEMBD * DINNER];
__device__ __align__(16) __half g_embh[(size_t)NVOCAB * NEMBD];

// ----------------------------- MMA helpers ---------------------------------
__device__ __forceinline__ void ldm_x4(uint32_t* r, uint32_t a) {
    asm volatile("ldmatrix.sync.aligned.m8n8.x4.shared.b16 {%0,%1,%2,%3}, [%4];"
                 : "=r"(r[0]), "=r"(r[1]), "=r"(r[2]), "=r"(r[3]) : "r"(a));
}
__device__ __forceinline__ void mma_16816(float* c, const uint32_t* a, const uint32_t* b) {
    asm volatile("mma.sync.aligned.m16n8k16.row.col.f32.f16.f16.f32 "
        "{%0,%1,%2,%3}, {%4,%5,%6,%7}, {%8,%9}, {%0,%1,%2,%3};"
        : "+f"(c[0]), "+f"(c[1]), "+f"(c[2]), "+f"(c[3])
        : "r"(a[0]), "r"(a[1]), "r"(a[2]), "r"(a[3]), "r"(b[0]), "r"(b[1]));
}

#define CPASYNC16(dst, src, sz) \
    asm volatile("cp.async.cg.shared.global [%0], [%1], 16, %2;" \
                 :: "r"(dst), "l"(src), "r"(sz))

// ------------- HMMA NT GEMM: C[M,N] (+)= sum_p A_p B^T ---------------------
// CTA 128x128, BK=64, 3-stage cp.async, 8 warps (2Mx4N), warp tile 64x32,
// 2 CTAs/SM (smem 110.6KB). A,B fp16 K-major; M%128==0, K%64==0, N guarded.
// (R8 config — benched 2974us; do not grow the COMPUTE body: reg budget 128.)
template <bool ACC>
__global__ __launch_bounds__(256, 2) void gemm_mma4(
    const uint16_t* __restrict__ A0, const uint16_t* __restrict__ A1,
    const uint16_t* __restrict__ B,
    int npass, float* __restrict__ C, int N, int K, int ldc) {
    extern __shared__ __align__(16) uint16_t sm[];
    constexpr int PITCH = 72;                // 64 halfs + 8 pad (144B rows)
    constexpr int ASTR = 128 * PITCH;
    constexpr int BSTR = 128 * PITCH;

    const int tid = threadIdx.x, lane = tid & 31, wid = tid >> 5;
    const int bm = blockIdx.x * 128, bn = blockIdx.y * 128;
    const int kc64 = K >> 6;
    const int NC = npass * kc64;

    const uint32_t smBase = (uint32_t)__cvta_generic_to_shared(sm);
    const int lrow = tid >> 3, lch = tid & 7;

    const int arow = (lane & 7) + ((lane >> 3) & 1) * 8;
    const int akc  = lane >> 4;
    const int brow = (lane & 7) + ((lane >> 4) << 3);
    const int bkc  = (lane >> 3) & 1;
    const int wm = (wid & 1) * 64;
    const int wn = (wid >> 1) * 32;

    float acc[4][4][4];
    #pragma unroll
    for (int i = 0; i < 4; i++)
        #pragma unroll
        for (int j = 0; j < 4; j++)
            #pragma unroll
            for (int k = 0; k < 4; k++) acc[i][j][k] = 0.f;

#define ISSUE(st, c) do { \
    int _p = (c) / kc64, _k = (c) - _p * kc64; \
    const uint16_t* _Aw = (_p == 0) ? A0 : A1; \
    _Pragma("unroll") \
    for (int _it = 0; _it < 4; _it++) { \
        int _r = lrow + _it * 32; \
        const uint16_t* _ga = _Aw + (size_t)(bm + _r) * K + _k * 64 + lch * 8; \
        uint32_t _da = smBase + 2u * ((st) * ASTR + _r * PITCH + lch * 8); \
        CPASYNC16(_da, _ga, 16); \
    } \
    _Pragma("unroll") \
    for (int _it = 0; _it < 4; _it++) { \
        int _r = lrow + _it * 32; \
        int _gr = bn + _r; \
        const uint16_t* _gb = B + (size_t)((_gr < N) ? _gr : 0) * K + _k * 64 + lch * 8; \
        uint32_t _db = smBase + 2u * (3 * ASTR + (st) * BSTR + _r * PITCH + lch * 8); \
        CPASYNC16(_db, _gb, (_gr < N) ? 16 : 0); \
    } \
  } while (0)

#define COMPUTE(st) do { \
    uint32_t _ab = smBase + 2u * ((st) * ASTR); \
    uint32_t _bb = smBase + 2u * (3 * ASTR + (st) * BSTR); \
    _Pragma("unroll") \
    for (int kk = 0; kk < 4; kk++) { \
        uint32_t af[4][4], bf[2][4]; \
        _Pragma("unroll") \
        for (int mi = 0; mi < 4; mi++) \
            ldm_x4(af[mi], _ab + 2u * ((wm + mi * 16 + arow) * PITCH + (kk * 2 + akc) * 8)); \
        _Pragma("unroll") \
        for (int nb = 0; nb < 2; nb++) \
            ldm_x4(bf[nb], _bb + 2u * ((wn + nb * 16 + brow) * PITCH + (kk * 2 + bkc) * 8)); \
        _Pragma("unroll") \
        for (int mi = 0; mi < 4; mi++) \
            _Pragma("unroll") \
            for (int ni = 0; ni < 4; ni++) \
                mma_16816(acc[mi][ni], af[mi], &bf[ni >> 1][(ni & 1) * 2]); \
    } \
  } while (0)

    ISSUE(0, 0);
    asm volatile("cp.async.commit_group;" ::: "memory");
    ISSUE(1, 1);
    asm volatile("cp.async.commit_group;" ::: "memory");

    for (int c = 0; c < NC; c++) {
        asm volatile("cp.async.wait_group 1;" ::: "memory");
        __syncthreads();
        if (c + 2 < NC) ISSUE((c + 2) % 3, c + 2);
        asm volatile("cp.async.commit_group;" ::: "memory");
        COMPUTE(c % 3);
    }
#undef ISSUE
#undef COMPUTE

    // epilogue
    const int gid = lane >> 2, q2 = (lane & 3) * 2;
    #pragma unroll
    for (int mi = 0; mi < 4; mi++) {
        const size_t row0 = (size_t)(bm + wm + mi * 16 + gid);
        const size_t row1 = row0 + 8;
        #pragma unroll
        for (int ni = 0; ni < 4; ni++) {
            const int col = bn + wn + ni * 8 + q2;
            const float* cf = acc[mi][ni];
            if (col < N) {
                if (ACC) { C[row0 * ldc + col] += cf[0]; C[row1 * ldc + col] += cf[2]; }
                else     { C[row0 * ldc + col]  = cf[0]; C[row1 * ldc + col]  = cf[2]; }
            }
            if (col + 1 < N) {
                if (ACC) { C[row0 * ldc + col + 1] += cf[1]; C[row1 * ldc + col + 1] += cf[3]; }
                else     { C[row0 * ldc + col + 1]  = cf[1]; C[row1 * ldc + col + 1]  = cf[3]; }
            }
        }
    }
}

#define SMEM_G (3 * (128 + 128) * 72 * 2)   // 110592 B

// ----------------------------- small helpers -------------------------------
__device__ __forceinline__ float sigm(float x) { return 1.0f / (1.0f + expf(-x)); }
__device__ __forceinline__ uint32_t packh2(float a, float b) {
    return (uint32_t)__half_as_ushort(__float2half_rn(a)) |
           ((uint32_t)__half_as_ushort(__float2half_rn(b)) << 16);
}
__device__ __forceinline__ void split2h(float a, float b, uint32_t& hi, uint32_t& lo) {
    __half ha = __float2half_rn(a), hb = __float2half_rn(b);
    float la = a - __half2float(ha), lb = b - __half2float(hb);
    hi = (uint32_t)__half_as_ushort(ha) | ((uint32_t)__half_as_ushort(hb) << 16);
    lo = packh2(la, lb);
}

// ----------------------------- conversions ---------------------------------
__global__ void convert_half_kernel(const float* __restrict__ src,
                                    __half* __restrict__ dst, int n4) {
    int i = blockIdx.x * blockDim.x + threadIdx.x;
    if (i >= n4) return;
    float4 v = reinterpret_cast<const float4*>(src)[i];
    uint2 o;
    o.x = packh2(v.x, v.y);
    o.y = packh2(v.z, v.w);
    reinterpret_cast<uint2*>(dst)[i] = o;
}

// ----------------------------- embedding gather ----------------------------
__global__ void embed_kernel(const int* __restrict__ tokens,
                             const float* __restrict__ emb,
                             float* __restrict__ x) {
    int l = blockIdx.x;
    int tok = tokens[l];
    const float4* src = reinterpret_cast<const float4*>(emb + (size_t)tok * NEMBD);
    float4* dst = reinterpret_cast<float4*>(x + (size_t)l * NEMBD);
    dst[threadIdx.x] = src[threadIdx.x];
}

// ---------------- rmsnorm (width 1024) with fp16 outputs -------------------
template <int OUT_MODE>   // 0: fp16 hi/lo; 1: fp16 single
__global__ void rmsnorm_out_kernel(const float* __restrict__ x,
                                   const float* __restrict__ w,
                                   const float* __restrict__ b,
                                   void* __restrict__ out_hi,
                                   void* __restrict__ out_lo) {
    int l = blockIdx.x;
    const float4* xr = reinterpret_cast<const float4*>(x + (size_t)l * NEMBD);
    float4 v = xr[threadIdx.x];
    float ss = v.x * v.x + v.y * v.y + v.z * v.z + v.w * v.w;
    #pragma unroll
    for (int o = 16; o > 0; o >>= 1) ss += __shfl_xor_sync(0xffffffffu, ss, o);
    __shared__ float wsum[8];
    __shared__ float inv_s;
    if ((threadIdx.x & 31) == 0) wsum[threadIdx.x >> 5] = ss;
    __syncthreads();
    if (threadIdx.x == 0) {
        float t = 0.f;
        #pragma unroll
        for (int k = 0; k < 8; k++) t += wsum[k];
        inv_s = rsqrtf(t / (float)NEMBD + 1e-6f);
    }
    __syncthreads();
    float inv = inv_s;
    float4 wv = reinterpret_cast<const float4*>(w)[threadIdx.x];
    float4 bv = reinterpret_cast<const float4*>(b)[threadIdx.x];
    float o0 = v.x * inv * wv.x + bv.x;
    float o1 = v.y * inv * wv.y + bv.y;
    float o2 = v.z * inv * wv.z + bv.z;
    float o3 = v.w * inv * wv.w + bv.w;
    size_t base = (size_t)l * NEMBD / 4 + threadIdx.x;
    if (OUT_MODE == 0) {
        uint2 h, lo;
        split2h(o0, o1, h.x, lo.x);
        split2h(o2, o3, h.y, lo.y);
        reinterpret_cast<uint2*>(out_hi)[base] = h;
        reinterpret_cast<uint2*>(out_lo)[base] = lo;
    } else {
        uint2 o;
        o.x = packh2(o0, o1);
        o.y = packh2(o2, o3);
        reinterpret_cast<uint2*>(out_hi)[base] = o;
    }
}

// ------------------- fp32 tiled NT GEMM (small GEMMs) ----------------------
// SOFTP: epilogue computes softplus(acc + bias[col]) (dt-proj fusion).
template <bool ACC, bool SPLIT, bool SOFTP>
__global__ __launch_bounds__(256) void gemm_nt(
    const float* __restrict__ A, const float* __restrict__ B,
    float* __restrict__ C, int M, int N, int K,
    int lda, int ldb, int ldc, int kchunk, long long cstride,
    const float* __restrict__ bias) {
    __shared__ float As[16][128 + 4];
    __shared__ float Bs[16][128 + 4];

    int k_begin = 0, k_end = K;
    if (SPLIT) {
        k_begin = blockIdx.z * kchunk;
        k_end = min(K, k_begin + kchunk);
        C += (long long)blockIdx.z * cstride;
    }
    const int bm = blockIdx.y * 128;
    const int bn = blockIdx.x * 128;
    const int tid = threadIdx.x;
    const int tx = tid & 15;
    const int ty = tid >> 4;

    float acc[8][8];
    #pragma unroll
    for (int i = 0; i < 8; i++)
        #pragma unroll
        for (int j = 0; j < 8; j++) acc[i][j] = 0.f;

    for (int k0 = k_begin; k0 < k_end; k0 += 16) {
        #pragma unroll
        for (int s = 0; s < 2; ++s) {
            int idx = tid + s * 256;
            int row = idx >> 2;
            int k4 = (idx & 3) * 4;
            float4 va = *reinterpret_cast<const float4*>(
                &A[(size_t)(bm + row) * lda + k0 + k4]);
            As[k4 + 0][row] = va.x; As[k4 + 1][row] = va.y;
            As[k4 + 2][row] = va.z; As[k4 + 3][row] = va.w;
            float4 vb;
            if (bn + row < N)
                vb = *reinterpret_cast<const float4*>(
                    &B[(size_t)(bn + row) * ldb + k0 + k4]);
            else
                vb = make_float4(0.f, 0.f, 0.f, 0.f);
            Bs[k4 + 0][row] = vb.x; Bs[k4 + 1][row] = vb.y;
            Bs[k4 + 2][row] = vb.z; Bs[k4 + 3][row] = vb.w;
        }
        __syncthreads();
        #pragma unroll
        for (int kk = 0; kk < 16; ++kk) {
            float a[8], b[8];
            *reinterpret_cast<float4*>(&a[0]) =
                *reinterpret_cast<const float4*>(&As[kk][ty * 4]);
            *reinterpret_cast<float4*>(&a[4]) =
                *reinterpret_cast<const float4*>(&As[kk][64 + ty * 4]);
            *reinterpret_cast<float4*>(&b[0]) =
                *reinterpret_cast<const float4*>(&Bs[kk][tx * 4]);
            *reinterpret_cast<float4*>(&b[4]) =
                *reinterpret_cast<const float4*>(&Bs[kk][64 + tx * 4]);
            #pragma unroll
            for (int i = 0; i < 8; i++)
                #pragma unroll
                for (int j = 0; j < 8; j++)
                    acc[i][j] = fmaf(a[i], b[j], acc[i][j]);
        }
        __syncthreads();
    }

    #pragma unroll
    for (int i = 0; i < 8; i++) {
        int ri = bm + ((i < 4) ? (ty * 4 + i) : (64 + ty * 4 + (i - 4)));
        #pragma unroll
        for (int j = 0; j < 8; j++) {
            int cj = bn + ((j < 4) ? (tx * 4 + j) : (64 + tx * 4 + (j - 4)));
            if (cj < N) {
                size_t off = (size_t)ri * ldc + cj;
                float v = acc[i][j];
                if (SOFTP) {
                    float t = v + bias[cj];
                    v = fmaxf(t, 0.f) + log1pf(expf(-fabsf(t)));
                }
                if (ACC) C[off] += v;
                else     C[off]  = v;
            }
        }
    }
}

__global__ void reduce_split_kernel(const float* __restrict__ part,
                                    float* __restrict__ out,
                                    int n, int nz, long long stride) {
    int i = blockIdx.x * blockDim.x + threadIdx.x;
    if (i < n) {
        float s = 0.f;
        for (int z = 0; z < nz; z++) s += part[(long long)z * stride + i];
        out[i] = s;
    }
}

// --------------------- depthwise causal conv + silu ------------------------
__global__ void conv_silu_kernel(const float* __restrict__ xr,
                                 const float* __restrict__ W,
                                 const float* __restrict__ b,
                                 float* __restrict__ u) {
    int idx = blockIdx.x * blockDim.x + threadIdx.x;
    int d = idx & (DINNER - 1);
    int l = idx >> 11;
    float acc = b[d];
    #pragma unroll
    for (int j = 0; j < DCONV; j++) {
        int t = l - (DCONV - 1) + j;
        if (t >= 0) acc = fmaf(xr[(size_t)t * (2 * DINNER) + d], W[d * DCONV + j], acc);
    }
    u[(size_t)l * DINNER + d] = acc * sigm(acc);
}

// ------ selective scan, gate fused with residual STAGED via shared mem -----
#define TCHUNK 64
__global__ __launch_bounds__(256) void scan_kernel(
    const float* __restrict__ delta, const float* __restrict__ u,
    const float* __restrict__ xdbl, const float* __restrict__ xr,
    const float* __restrict__ A_log, const float* __restrict__ Dp,
    __half* __restrict__ yh, __half* __restrict__ yl) {
    const int lane_n = threadIdx.x & 15;
    const int ch_loc = threadIdx.x >> 4;
    const int d = blockIdx.x * 16 + ch_loc;
    const float Aneg = -expf(A_log[(size_t)d * DSTATE + lane_n]);
    const float Dval = Dp[d];
    float s = 0.f;

    __shared__ float Bsh[TCHUNK][16];
    __shared__ float Csh[TCHUNK][16];
    __shared__ float dsh[TCHUNK][16];
    __shared__ float ush[TCHUNK][16];
    __shared__ float rsh[TCHUNK][16];   // staged silu-gate residual

    for (int t0 = 0; t0 < LSEQ; t0 += TCHUNK) {
        __syncthreads();
        for (int i = threadIdx.x; i < TCHUNK * 16; i += 256) {
            int tt = i >> 4, n = i & 15;
            size_t trow = (size_t)(t0 + tt);
            Bsh[tt][n] = xdbl[trow * XDBL_W + DTRANK + n];
            Csh[tt][n] = xdbl[trow * XDBL_W + DTRANK + DSTATE + n];
            dsh[tt][n] = delta[trow * DINNER + blockIdx.x * 16 + n];
            ush[tt][n] = u    [trow * DINNER + blockIdx.x * 16 + n];
            rsh[tt][n] = xr   [trow * (2 * DINNER) + DINNER + blockIdx.x * 16 + n];
        }
        __syncthreads();
        #pragma unroll 4
        for (int tt = 0; tt < TCHUNK; ++tt) {
            float dt = dsh[tt][ch_loc];
            float uu = ush[tt][ch_loc];
            float dA = __expf(dt * Aneg);
            float dBu = dt * uu * Bsh[tt][lane_n];
            s = fmaf(dA, s, dBu);
            float yv = s * Csh[tt][lane_n];
            yv += __shfl_xor_sync(0xffffffffu, yv, 8);
            yv += __shfl_xor_sync(0xffffffffu, yv, 4);
            yv += __shfl_xor_sync(0xffffffffu, yv, 2);
            yv += __shfl_xor_sync(0xffffffffu, yv, 1);
            if (lane_n == 0) {
                size_t trow = (size_t)(t0 + tt);
                float g = yv + Dval * uu;
                float r = rsh[tt][ch_loc];
                g *= r * sigm(r);
                __half gh = __float2half_rn(g);
                yh[trow * DINNER + d] = gh;
                yl[trow * DINNER + d] = __float2half_rn(g - __half2float(gh));
            }
        }
    }
}

// ------------------------------- launcher ----------------------------------
extern "C" void kernel_launch(void* const* d_in, const int* in_sizes, int n_in,
                              void* d_out, int out_size) {
    const int*   tokens    = (const int*)  d_in[0];
    const float* emb_W     = (const float*)d_in[1];
    const float* in_proj_W = (const float*)d_in[2];
    const float* conv_W    = (const float*)d_in[3];
    const float* conv_b    = (const float*)d_in[4];
    const float* xproj_W   = (const float*)d_in[5];
    const float* dt_W      = (const float*)d_in[6];
    const float* dt_b      = (const float*)d_in[7];
    const float* A_log     = (const float*)d_in[8];
    const float* Dp        = (const float*)d_in[9];
    const float* out_W     = (const float*)d_in[10];
    const float* rms_w     = (const float*)d_in[11];
    const float* rms_b     = (const float*)d_in[12];
    const float* normf_w   = (const float*)d_in[13];
    const float* normf_b   = (const float*)d_in[14];
    float* out = (float*)d_out;

    float *px, *pxr, *pu, *pxdbl, *pdelta, *ppart;
    __half *phh, *phl, *pyh, *pyl, *pwi, *pwo, *pembh;
    cudaGetSymbolAddress((void**)&px,     g_x);
    cudaGetSymbolAddress((void**)&pxr,    g_xr);
    cudaGetSymbolAddress((void**)&pu,     g_u);
    cudaGetSymbolAddress((void**)&pxdbl,  g_xdbl);
    cudaGetSymbolAddress((void**)&pdelta, g_delta);
    cudaGetSymbolAddress((void**)&ppart,  g_part);
    cudaGetSymbolAddress((void**)&phh,    g_hh);
    cudaGetSymbolAddress((void**)&phl,    g_hl);
    cudaGetSymbolAddress((void**)&pyh,    g_yh);
    cudaGetSymbolAddress((void**)&pyl,    g_yl);
    cudaGetSymbolAddress((void**)&pwi,    g_wi);
    cudaGetSymbolAddress((void**)&pwo,    g_wo);
    cudaGetSymbolAddress((void**)&pembh,  g_embh);

    cudaFuncSetAttribute(gemm_mma4<false>,
        cudaFuncAttributeMaxDynamicSharedMemorySize, SMEM_G);
    cudaFuncSetAttribute(gemm_mma4<true>,
        cudaFuncAttributeMaxDynamicSharedMemorySize, SMEM_G);

    // ---- weight conversions to fp16 (every launch; deterministic) ----
    {
        int n4 = NLAYERS * 2 * DINNER * NEMBD / 4;
        convert_half_kernel<<<(n4 + 255) / 256, 256>>>(in_proj_W, pwi, n4);
        n4 = NLAYERS * NEMBD * DINNER / 4;
        convert_half_kernel<<<(n4 + 255) / 256, 256>>>(out_W, pwo, n4);
        n4 = (int)((size_t)NVOCAB * NEMBD / 4);
        convert_half_kernel<<<(n4 + 255) / 256, 256>>>(emb_W, pembh, n4);
    }

    embed_kernel<<<LSEQ, 256>>>(tokens, emb_W, px);

    for (int i = 0; i < NLAYERS; i++) {
        rmsnorm_out_kernel<0><<<LSEQ, 256>>>(px, rms_w + i * NEMBD,
                                             rms_b + i * NEMBD, phh, phl);

        // in_proj: xr[L,4096] = h @ W^T  (fp16 hi/lo 2-pass)
        {
            const uint16_t* bw = (const uint16_t*)(pwi + (size_t)i * 2 * DINNER * NEMBD);
            dim3 g(LSEQ / 128, 2 * DINNER / 128);
            gemm_mma4<false><<<g, 256, SMEM_G>>>(
                (const uint16_t*)phh, (const uint16_t*)phl, bw,
                2, pxr, 2 * DINNER, NEMBD, 2 * DINNER);
        }

        conv_silu_kernel<<<LSEQ * DINNER / 256, 256>>>(
            pxr, conv_W + (size_t)i * DINNER * DCONV, conv_b + i * DINNER, pu);

        // x_proj (N=96): split-K fp32
        {
            dim3 grid(1, LSEQ / 128, 8);
            gemm_nt<false, true, false><<<grid, 256>>>(
                pu, xproj_W + (size_t)i * XDBL_W * DINNER, ppart,
                LSEQ, XDBL_W, DINNER, DINNER, DINNER, XDBL_W,
                DINNER / 8, (long long)LSEQ * XDBL_W, nullptr);
            int n = LSEQ * XDBL_W;
            reduce_split_kernel<<<(n + 255) / 256, 256>>>(
                ppart, pxdbl, n, 8, (long long)LSEQ * XDBL_W);
        }

        // dt proj + fused softplus
        {
            dim3 grid(DINNER / 128, LSEQ / 128);
            gemm_nt<false, false, true><<<grid, 256>>>(
                pxdbl, dt_W + (size_t)i * DINNER * DTRANK, pdelta,
                LSEQ, DINNER, DTRANK, XDBL_W, DTRANK, DINNER, 0, 0,
                dt_b + i * DINNER);
        }

        // scan + fused gate (residual staged in smem) + fp16 split
        scan_kernel<<<DINNER / 16, 256>>>(
            pdelta, pu, pxdbl, pxr,
            A_log + (size_t)i * DINNER * DSTATE, Dp + i * DINNER, pyh, pyl);

        // out_proj accumulate: x += y @ out_W^T  (fp16 hi/lo 2-pass)
        {
            const uint16_t* bw = (const uint16_t*)(pwo + (size_t)i * NEMBD * DINNER);
            dim3 g(LSEQ / 128, NEMBD / 128);
            gemm_mma4<true><<<g, 256, SMEM_G>>>(
                (const uint16_t*)pyh, (const uint16_t*)pyl, bw,
                2, px, NEMBD, DINNER, NEMBD);
        }
    }

    // final norm (fp16 out) + tied lm head (fp16 single pass)
    rmsnorm_out_kernel<1><<<LSEQ, 256>>>(px, normf_w, normf_b, phh, nullptr);
    {
        dim3 g(LSEQ / 128, (NVOCAB + 127) / 128);
        const uint16_t* ah = (const uint16_t*)phh;
        const uint16_t* bh = (const uint16_t*)pembh;
        gemm_mma4<false><<<g, 256, SMEM_G>>>(
            ah, ah, bh, 1, out, NVOCAB, NEMBD, NVOCAB);
    }
}

// round 14
// speedup vs baseline: 2.0415x; 1.1104x over previous
#include <cuda_runtime.h>
#include <cuda_bf16.h>
#include <cuda_fp16.h>
#include <math.h>
#include <stdint.h>

// ---------------------------------------------------------------------------
// Mamba forward, L=2048, 4 layers.
// Big GEMMs via mma.sync (HMMA fp16), CTA 128x128, BK=64, 3-stage cp.async,
// 2 CTAs/SM: layer GEMMs = fp16 activation-hi/lo 2-pass, lm head = 1-pass.
// Small GEMMs + elementwise in fp32 SIMT; softplus fused into dt GEMM.
// Scan: serial loop stores raw y to smem (tiny predicated STS only);
// gate + fp16 split done in a bulk coalesced phase per 64-step chunk.
// ---------------------------------------------------------------------------

#define LSEQ    2048
#define NEMBD   1024
#define DINNER  2048
#define DSTATE  16
#define DTRANK  64
#define DCONV   4
#define NVOCAB  50257
#define NLAYERS 4
#define XDBL_W  (DTRANK + 2 * DSTATE)   // 96

// ----------------------------- scratch (static) ----------------------------
__device__ __align__(16) float g_x    [LSEQ * NEMBD];
__device__ __align__(16) float g_xr   [LSEQ * 2 * DINNER];
__device__ __align__(16) float g_u    [LSEQ * DINNER];
__device__ __align__(16) float g_xdbl [LSEQ * XDBL_W];
__device__ __align__(16) float g_delta[LSEQ * DINNER];
__device__ __align__(16) float g_part [8 * LSEQ * XDBL_W];

__device__ __align__(16) __half g_hh [LSEQ * NEMBD];    // activations hi
__device__ __align__(16) __half g_hl [LSEQ * NEMBD];    // activations lo
__device__ __align__(16) __half g_yh [LSEQ * DINNER];
__device__ __align__(16) __half g_yl [LSEQ * DINNER];
__device__ __align__(16) __half g_wi [NLAYERS * 2 * DINNER * NEMBD];
__device__ __align__(16) __half g_wo [NLAYERS * NEMBD * DINNER];
__device__ __align__(16) __half g_embh[(size_t)NVOCAB * NEMBD];

// ----------------------------- MMA helpers ---------------------------------
__device__ __forceinline__ void ldm_x4(uint32_t* r, uint32_t a) {
    asm volatile("ldmatrix.sync.aligned.m8n8.x4.shared.b16 {%0,%1,%2,%3}, [%4];"
                 : "=r"(r[0]), "=r"(r[1]), "=r"(r[2]), "=r"(r[3]) : "r"(a));
}
__device__ __forceinline__ void mma_16816(float* c, const uint32_t* a, const uint32_t* b) {
    asm volatile("mma.sync.aligned.m16n8k16.row.col.f32.f16.f16.f32 "
        "{%0,%1,%2,%3}, {%4,%5,%6,%7}, {%8,%9}, {%0,%1,%2,%3};"
        : "+f"(c[0]), "+f"(c[1]), "+f"(c[2]), "+f"(c[3])
        : "r"(a[0]), "r"(a[1]), "r"(a[2]), "r"(a[3]), "r"(b[0]), "r"(b[1]));
}

#define CPASYNC16(dst, src, sz) \
    asm volatile("cp.async.cg.shared.global [%0], [%1], 16, %2;" \
                 :: "r"(dst), "l"(src), "r"(sz))

// ------------- HMMA NT GEMM: C[M,N] (+)= sum_p A_p B^T ---------------------
// CTA 128x128, BK=64, 3-stage cp.async, 8 warps (2Mx4N), warp tile 64x32,
// 2 CTAs/SM (smem 110.6KB). A,B fp16 K-major; M%128==0, K%64==0, N guarded.
// (R8 config — benched 2974us; do not grow the COMPUTE body: reg budget 128.)
template <bool ACC>
__global__ __launch_bounds__(256, 2) void gemm_mma4(
    const uint16_t* __restrict__ A0, const uint16_t* __restrict__ A1,
    const uint16_t* __restrict__ B,
    int npass, float* __restrict__ C, int N, int K, int ldc) {
    extern __shared__ __align__(16) uint16_t sm[];
    constexpr int PITCH = 72;                // 64 halfs + 8 pad (144B rows)
    constexpr int ASTR = 128 * PITCH;
    constexpr int BSTR = 128 * PITCH;

    const int tid = threadIdx.x, lane = tid & 31, wid = tid >> 5;
    const int bm = blockIdx.x * 128, bn = blockIdx.y * 128;
    const int kc64 = K >> 6;
    const int NC = npass * kc64;

    const uint32_t smBase = (uint32_t)__cvta_generic_to_shared(sm);
    const int lrow = tid >> 3, lch = tid & 7;

    const int arow = (lane & 7) + ((lane >> 3) & 1) * 8;
    const int akc  = lane >> 4;
    const int brow = (lane & 7) + ((lane >> 4) << 3);
    const int bkc  = (lane >> 3) & 1;
    const int wm = (wid & 1) * 64;
    const int wn = (wid >> 1) * 32;

    float acc[4][4][4];
    #pragma unroll
    for (int i = 0; i < 4; i++)
        #pragma unroll
        for (int j = 0; j < 4; j++)
            #pragma unroll
            for (int k = 0; k < 4; k++) acc[i][j][k] = 0.f;

#define ISSUE(st, c) do { \
    int _p = (c) / kc64, _k = (c) - _p * kc64; \
    const uint16_t* _Aw = (_p == 0) ? A0 : A1; \
    _Pragma("unroll") \
    for (int _it = 0; _it < 4; _it++) { \
        int _r = lrow + _it * 32; \
        const uint16_t* _ga = _Aw + (size_t)(bm + _r) * K + _k * 64 + lch * 8; \
        uint32_t _da = smBase + 2u * ((st) * ASTR + _r * PITCH + lch * 8); \
        CPASYNC16(_da, _ga, 16); \
    } \
    _Pragma("unroll") \
    for (int _it = 0; _it < 4; _it++) { \
        int _r = lrow + _it * 32; \
        int _gr = bn + _r; \
        const uint16_t* _gb = B + (size_t)((_gr < N) ? _gr : 0) * K + _k * 64 + lch * 8; \
        uint32_t _db = smBase + 2u * (3 * ASTR + (st) * BSTR + _r * PITCH + lch * 8); \
        CPASYNC16(_db, _gb, (_gr < N) ? 16 : 0); \
    } \
  } while (0)

#define COMPUTE(st) do { \
    uint32_t _ab = smBase + 2u * ((st) * ASTR); \
    uint32_t _bb = smBase + 2u * (3 * ASTR + (st) * BSTR); \
    _Pragma("unroll") \
    for (int kk = 0; kk < 4; kk++) { \
        uint32_t af[4][4], bf[2][4]; \
        _Pragma("unroll") \
        for (int mi = 0; mi < 4; mi++) \
            ldm_x4(af[mi], _ab + 2u * ((wm + mi * 16 + arow) * PITCH + (kk * 2 + akc) * 8)); \
        _Pragma("unroll") \
        for (int nb = 0; nb < 2; nb++) \
            ldm_x4(bf[nb], _bb + 2u * ((wn + nb * 16 + brow) * PITCH + (kk * 2 + bkc) * 8)); \
        _Pragma("unroll") \
        for (int mi = 0; mi < 4; mi++) \
            _Pragma("unroll") \
            for (int ni = 0; ni < 4; ni++) \
                mma_16816(acc[mi][ni], af[mi], &bf[ni >> 1][(ni & 1) * 2]); \
    } \
  } while (0)

    ISSUE(0, 0);
    asm volatile("cp.async.commit_group;" ::: "memory");
    ISSUE(1, 1);
    asm volatile("cp.async.commit_group;" ::: "memory");

    for (int c = 0; c < NC; c++) {
        asm volatile("cp.async.wait_group 1;" ::: "memory");
        __syncthreads();
        if (c + 2 < NC) ISSUE((c + 2) % 3, c + 2);
        asm volatile("cp.async.commit_group;" ::: "memory");
        COMPUTE(c % 3);
    }
#undef ISSUE
#undef COMPUTE

    // epilogue
    const int gid = lane >> 2, q2 = (lane & 3) * 2;
    #pragma unroll
    for (int mi = 0; mi < 4; mi++) {
        const size_t row0 = (size_t)(bm + wm + mi * 16 + gid);
        const size_t row1 = row0 + 8;
        #pragma unroll
        for (int ni = 0; ni < 4; ni++) {
            const int col = bn + wn + ni * 8 + q2;
            const float* cf = acc[mi][ni];
            if (col < N) {
                if (ACC) { C[row0 * ldc + col] += cf[0]; C[row1 * ldc + col] += cf[2]; }
                else     { C[row0 * ldc + col]  = cf[0]; C[row1 * ldc + col]  = cf[2]; }
            }
            if (col + 1 < N) {
                if (ACC) { C[row0 * ldc + col + 1] += cf[1]; C[row1 * ldc + col + 1] += cf[3]; }
                else     { C[row0 * ldc + col + 1]  = cf[1]; C[row1 * ldc + col + 1]  = cf[3]; }
            }
        }
    }
}

#define SMEM_G (3 * (128 + 128) * 72 * 2)   // 110592 B

// ----------------------------- small helpers -------------------------------
__device__ __forceinline__ float sigm(float x) { return 1.0f / (1.0f + expf(-x)); }
__device__ __forceinline__ uint32_t packh2(float a, float b) {
    return (uint32_t)__half_as_ushort(__float2half_rn(a)) |
           ((uint32_t)__half_as_ushort(__float2half_rn(b)) << 16);
}
__device__ __forceinline__ void split2h(float a, float b, uint32_t& hi, uint32_t& lo) {
    __half ha = __float2half_rn(a), hb = __float2half_rn(b);
    float la = a - __half2float(ha), lb = b - __half2float(hb);
    hi = (uint32_t)__half_as_ushort(ha) | ((uint32_t)__half_as_ushort(hb) << 16);
    lo = packh2(la, lb);
}

// ----------------------------- conversions ---------------------------------
__global__ void convert_half_kernel(const float* __restrict__ src,
                                    __half* __restrict__ dst, int n4) {
    int i = blockIdx.x * blockDim.x + threadIdx.x;
    if (i >= n4) return;
    float4 v = reinterpret_cast<const float4*>(src)[i];
    uint2 o;
    o.x = packh2(v.x, v.y);
    o.y = packh2(v.z, v.w);
    reinterpret_cast<uint2*>(dst)[i] = o;
}

// ----------------------------- embedding gather ----------------------------
__global__ void embed_kernel(const int* __restrict__ tokens,
                             const float* __restrict__ emb,
                             float* __restrict__ x) {
    int l = blockIdx.x;
    int tok = tokens[l];
    const float4* src = reinterpret_cast<const float4*>(emb + (size_t)tok * NEMBD);
    float4* dst = reinterpret_cast<float4*>(x + (size_t)l * NEMBD);
    dst[threadIdx.x] = src[threadIdx.x];
}

// ---------------- rmsnorm (width 1024) with fp16 outputs -------------------
template <int OUT_MODE>   // 0: fp16 hi/lo; 1: fp16 single
__global__ void rmsnorm_out_kernel(const float* __restrict__ x,
                                   const float* __restrict__ w,
                                   const float* __restrict__ b,
                                   void* __restrict__ out_hi,
                                   void* __restrict__ out_lo) {
    int l = blockIdx.x;
    const float4* xr = reinterpret_cast<const float4*>(x + (size_t)l * NEMBD);
    float4 v = xr[threadIdx.x];
    float ss = v.x * v.x + v.y * v.y + v.z * v.z + v.w * v.w;
    #pragma unroll
    for (int o = 16; o > 0; o >>= 1) ss += __shfl_xor_sync(0xffffffffu, ss, o);
    __shared__ float wsum[8];
    __shared__ float inv_s;
    if ((threadIdx.x & 31) == 0) wsum[threadIdx.x >> 5] = ss;
    __syncthreads();
    if (threadIdx.x == 0) {
        float t = 0.f;
        #pragma unroll
        for (int k = 0; k < 8; k++) t += wsum[k];
        inv_s = rsqrtf(t / (float)NEMBD + 1e-6f);
    }
    __syncthreads();
    float inv = inv_s;
    float4 wv = reinterpret_cast<const float4*>(w)[threadIdx.x];
    float4 bv = reinterpret_cast<const float4*>(b)[threadIdx.x];
    float o0 = v.x * inv * wv.x + bv.x;
    float o1 = v.y * inv * wv.y + bv.y;
    float o2 = v.z * inv * wv.z + bv.z;
    float o3 = v.w * inv * wv.w + bv.w;
    size_t base = (size_t)l * NEMBD / 4 + threadIdx.x;
    if (OUT_MODE == 0) {
        uint2 h, lo;
        split2h(o0, o1, h.x, lo.x);
        split2h(o2, o3, h.y, lo.y);
        reinterpret_cast<uint2*>(out_hi)[base] = h;
        reinterpret_cast<uint2*>(out_lo)[base] = lo;
    } else {
        uint2 o;
        o.x = packh2(o0, o1);
        o.y = packh2(o2, o3);
        reinterpret_cast<uint2*>(out_hi)[base] = o;
    }
}

// ------------------- fp32 tiled NT GEMM (small GEMMs) ----------------------
// SOFTP: epilogue computes softplus(acc + bias[col]) (dt-proj fusion).
template <bool ACC, bool SPLIT, bool SOFTP>
__global__ __launch_bounds__(256) void gemm_nt(
    const float* __restrict__ A, const float* __restrict__ B,
    float* __restrict__ C, int M, int N, int K,
    int lda, int ldb, int ldc, int kchunk, long long cstride,
    const float* __restrict__ bias) {
    __shared__ float As[16][128 + 4];
    __shared__ float Bs[16][128 + 4];

    int k_begin = 0, k_end = K;
    if (SPLIT) {
        k_begin = blockIdx.z * kchunk;
        k_end = min(K, k_begin + kchunk);
        C += (long long)blockIdx.z * cstride;
    }
    const int bm = blockIdx.y * 128;
    const int bn = blockIdx.x * 128;
    const int tid = threadIdx.x;
    const int tx = tid & 15;
    const int ty = tid >> 4;

    float acc[8][8];
    #pragma unroll
    for (int i = 0; i < 8; i++)
        #pragma unroll
        for (int j = 0; j < 8; j++) acc[i][j] = 0.f;

    for (int k0 = k_begin; k0 < k_end; k0 += 16) {
        #pragma unroll
        for (int s = 0; s < 2; ++s) {
            int idx = tid + s * 256;
            int row = idx >> 2;
            int k4 = (idx & 3) * 4;
            float4 va = *reinterpret_cast<const float4*>(
                &A[(size_t)(bm + row) * lda + k0 + k4]);
            As[k4 + 0][row] = va.x; As[k4 + 1][row] = va.y;
            As[k4 + 2][row] = va.z; As[k4 + 3][row] = va.w;
            float4 vb;
            if (bn + row < N)
                vb = *reinterpret_cast<const float4*>(
                    &B[(size_t)(bn + row) * ldb + k0 + k4]);
            else
                vb = make_float4(0.f, 0.f, 0.f, 0.f);
            Bs[k4 + 0][row] = vb.x; Bs[k4 + 1][row] = vb.y;
            Bs[k4 + 2][row] = vb.z; Bs[k4 + 3][row] = vb.w;
        }
        __syncthreads();
        #pragma unroll
        for (int kk = 0; kk < 16; ++kk) {
            float a[8], b[8];
            *reinterpret_cast<float4*>(&a[0]) =
                *reinterpret_cast<const float4*>(&As[kk][ty * 4]);
            *reinterpret_cast<float4*>(&a[4]) =
                *reinterpret_cast<const float4*>(&As[kk][64 + ty * 4]);
            *reinterpret_cast<float4*>(&b[0]) =
                *reinterpret_cast<const float4*>(&Bs[kk][tx * 4]);
            *reinterpret_cast<float4*>(&b[4]) =
                *reinterpret_cast<const float4*>(&Bs[kk][64 + tx * 4]);
            #pragma unroll
            for (int i = 0; i < 8; i++)
                #pragma unroll
                for (int j = 0; j < 8; j++)
                    acc[i][j] = fmaf(a[i], b[j], acc[i][j]);
        }
        __syncthreads();
    }

    #pragma unroll
    for (int i = 0; i < 8; i++) {
        int ri = bm + ((i < 4) ? (ty * 4 + i) : (64 + ty * 4 + (i - 4)));
        #pragma unroll
        for (int j = 0; j < 8; j++) {
            int cj = bn + ((j < 4) ? (tx * 4 + j) : (64 + tx * 4 + (j - 4)));
            if (cj < N) {
                size_t off = (size_t)ri * ldc + cj;
                float v = acc[i][j];
                if (SOFTP) {
                    float t = v + bias[cj];
                    v = fmaxf(t, 0.f) + log1pf(expf(-fabsf(t)));
                }
                if (ACC) C[off] += v;
                else     C[off]  = v;
            }
        }
    }
}

__global__ void reduce_split_kernel(const float* __restrict__ part,
                                    float* __restrict__ out,
                                    int n, int nz, long long stride) {
    int i = blockIdx.x * blockDim.x + threadIdx.x;
    if (i < n) {
        float s = 0.f;
        for (int z = 0; z < nz; z++) s += part[(long long)z * stride + i];
        out[i] = s;
    }
}

// --------------------- depthwise causal conv + silu ------------------------
__global__ void conv_silu_kernel(const float* __restrict__ xr,
                                 const float* __restrict__ W,
                                 const float* __restrict__ b,
                                 float* __restrict__ u) {
    int idx = blockIdx.x * blockDim.x + threadIdx.x;
    int d = idx & (DINNER - 1);
    int l = idx >> 11;
    float acc = b[d];
    #pragma unroll
    for (int j = 0; j < DCONV; j++) {
        int t = l - (DCONV - 1) + j;
        if (t >= 0) acc = fmaf(xr[(size_t)t * (2 * DINNER) + d], W[d * DCONV + j], acc);
    }
    u[(size_t)l * DINNER + d] = acc * sigm(acc);
}

// -------- selective scan: minimal serial loop, bulk gate per chunk ---------
// Serial loop stores raw y = yv + D*u to smem only (tiny predicated STS).
// After each chunk, all 256 threads apply the gate + fp16 split with
// coalesced global stores. Math per element identical to the separate
// gate kernel (bit-identical output).
#define TCHUNK 64
__global__ __launch_bounds__(256) void scan_kernel(
    const float* __restrict__ delta, const float* __restrict__ u,
    const float* __restrict__ xdbl, const float* __restrict__ xr,
    const float* __restrict__ A_log, const float* __restrict__ Dp,
    __half* __restrict__ yh, __half* __restrict__ yl) {
    const int lane_n = threadIdx.x & 15;
    const int ch_loc = threadIdx.x >> 4;
    const int d = blockIdx.x * 16 + ch_loc;
    const float Aneg = -expf(A_log[(size_t)d * DSTATE + lane_n]);
    const float Dval = Dp[d];
    float s = 0.f;

    __shared__ float Bsh[TCHUNK][16];
    __shared__ float Csh[TCHUNK][16];
    __shared__ float dsh[TCHUNK][16];
    __shared__ float ush[TCHUNK][16];
    __shared__ float rsh[TCHUNK][16];   // staged silu-gate residual
    __shared__ float gsh[TCHUNK][16];   // raw scan output (pre-gate)

    for (int t0 = 0; t0 < LSEQ; t0 += TCHUNK) {
        __syncthreads();
        for (int i = threadIdx.x; i < TCHUNK * 16; i += 256) {
            int tt = i >> 4, n = i & 15;
            size_t trow = (size_t)(t0 + tt);
            Bsh[tt][n] = xdbl[trow * XDBL_W + DTRANK + n];
            Csh[tt][n] = xdbl[trow * XDBL_W + DTRANK + DSTATE + n];
            dsh[tt][n] = delta[trow * DINNER + blockIdx.x * 16 + n];
            ush[tt][n] = u    [trow * DINNER + blockIdx.x * 16 + n];
            rsh[tt][n] = xr   [trow * (2 * DINNER) + DINNER + blockIdx.x * 16 + n];
        }
        __syncthreads();
        #pragma unroll 4
        for (int tt = 0; tt < TCHUNK; ++tt) {
            float dt = dsh[tt][ch_loc];
            float uu = ush[tt][ch_loc];
            float dA = __expf(dt * Aneg);
            float dBu = dt * uu * Bsh[tt][lane_n];
            s = fmaf(dA, s, dBu);
            float yv = s * Csh[tt][lane_n];
            yv += __shfl_xor_sync(0xffffffffu, yv, 8);
            yv += __shfl_xor_sync(0xffffffffu, yv, 4);
            yv += __shfl_xor_sync(0xffffffffu, yv, 2);
            yv += __shfl_xor_sync(0xffffffffu, yv, 1);
            if (lane_n == 0)
                gsh[tt][ch_loc] = yv + Dval * uu;    // tiny predicated STS
        }
        __syncthreads();
        // bulk gate + fp16 split, coalesced stores (n fastest)
        for (int i = threadIdx.x; i < TCHUNK * 16; i += 256) {
            int tt = i >> 4, n = i & 15;
            float g = gsh[tt][n];
            float r = rsh[tt][n];
            g *= r * sigm(r);
            __half gh = __float2half_rn(g);
            size_t off = (size_t)(t0 + tt) * DINNER + blockIdx.x * 16 + n;
            yh[off] = gh;
            yl[off] = __float2half_rn(g - __half2float(gh));
        }
    }
}

// ------------------------------- launcher ----------------------------------
extern "C" void kernel_launch(void* const* d_in, const int* in_sizes, int n_in,
                              void* d_out, int out_size) {
    const int*   tokens    = (const int*)  d_in[0];
    const float* emb_W     = (const float*)d_in[1];
    const float* in_proj_W = (const float*)d_in[2];
    const float* conv_W    = (const float*)d_in[3];
    const float* conv_b    = (const float*)d_in[4];
    const float* xproj_W   = (const float*)d_in[5];
    const float* dt_W      = (const float*)d_in[6];
    const float* dt_b      = (const float*)d_in[7];
    const float* A_log     = (const float*)d_in[8];
    const float* Dp        = (const float*)d_in[9];
    const float* out_W     = (const float*)d_in[10];
    const float* rms_w     = (const float*)d_in[11];
    const float* rms_b     = (const float*)d_in[12];
    const float* normf_w   = (const float*)d_in[13];
    const float* normf_b   = (const float*)d_in[14];
    float* out = (float*)d_out;

    float *px, *pxr, *pu, *pxdbl, *pdelta, *ppart;
    __half *phh, *phl, *pyh, *pyl, *pwi, *pwo, *pembh;
    cudaGetSymbolAddress((void**)&px,     g_x);
    cudaGetSymbolAddress((void**)&pxr,    g_xr);
    cudaGetSymbolAddress((void**)&pu,     g_u);
    cudaGetSymbolAddress((void**)&pxdbl,  g_xdbl);
    cudaGetSymbolAddress((void**)&pdelta, g_delta);
    cudaGetSymbolAddress((void**)&ppart,  g_part);
    cudaGetSymbolAddress((void**)&phh,    g_hh);
    cudaGetSymbolAddress((void**)&phl,    g_hl);
    cudaGetSymbolAddress((void**)&pyh,    g_yh);
    cudaGetSymbolAddress((void**)&pyl,    g_yl);
    cudaGetSymbolAddress((void**)&pwi,    g_wi);
    cudaGetSymbolAddress((void**)&pwo,    g_wo);
    cudaGetSymbolAddress((void**)&pembh,  g_embh);

    cudaFuncSetAttribute(gemm_mma4<false>,
        cudaFuncAttributeMaxDynamicSharedMemorySize, SMEM_G);
    cudaFuncSetAttribute(gemm_mma4<true>,
        cudaFuncAttributeMaxDynamicSharedMemorySize, SMEM_G);

    // ---- weight conversions to fp16 (every launch; deterministic) ----
    {
        int n4 = NLAYERS * 2 * DINNER * NEMBD / 4;
        convert_half_kernel<<<(n4 + 255) / 256, 256>>>(in_proj_W, pwi, n4);
        n4 = NLAYERS * NEMBD * DINNER / 4;
        convert_half_kernel<<<(n4 + 255) / 256, 256>>>(out_W, pwo, n4);
        n4 = (int)((size_t)NVOCAB * NEMBD / 4);
        convert_half_kernel<<<(n4 + 255) / 256, 256>>>(emb_W, pembh, n4);
    }

    embed_kernel<<<LSEQ, 256>>>(tokens, emb_W, px);

    for (int i = 0; i < NLAYERS; i++) {
        rmsnorm_out_kernel<0><<<LSEQ, 256>>>(px, rms_w + i * NEMBD,
                                             rms_b + i * NEMBD, phh, phl);

        // in_proj: xr[L,4096] = h @ W^T  (fp16 hi/lo 2-pass)
        {
            const uint16_t* bw = (const uint16_t*)(pwi + (size_t)i * 2 * DINNER * NEMBD);
            dim3 g(LSEQ / 128, 2 * DINNER / 128);
            gemm_mma4<false><<<g, 256, SMEM_G>>>(
                (const uint16_t*)phh, (const uint16_t*)phl, bw,
                2, pxr, 2 * DINNER, NEMBD, 2 * DINNER);
        }

        conv_silu_kernel<<<LSEQ * DINNER / 256, 256>>>(
            pxr, conv_W + (size_t)i * DINNER * DCONV, conv_b + i * DINNER, pu);

        // x_proj (N=96): split-K fp32
        {
            dim3 grid(1, LSEQ / 128, 8);
            gemm_nt<false, true, false><<<grid, 256>>>(
                pu, xproj_W + (size_t)i * XDBL_W * DINNER, ppart,
                LSEQ, XDBL_W, DINNER, DINNER, DINNER, XDBL_W,
                DINNER / 8, (long long)LSEQ * XDBL_W, nullptr);
            int n = LSEQ * XDBL_W;
            reduce_split_kernel<<<(n + 255) / 256, 256>>>(
                ppart, pxdbl, n, 8, (long long)LSEQ * XDBL_W);
        }

        // dt proj + fused softplus
        {
            dim3 grid(DINNER / 128, LSEQ / 128);
            gemm_nt<false, false, true><<<grid, 256>>>(
                pxdbl, dt_W + (size_t)i * DINNER * DTRANK, pdelta,
                LSEQ, DINNER, DTRANK, XDBL_W, DTRANK, DINNER, 0, 0,
                dt_b + i * DINNER);
        }

        // scan (minimal serial loop) + bulk gate + fp16 split
        scan_kernel<<<DINNER / 16, 256>>>(
            pdelta, pu, pxdbl, pxr,
            A_log + (size_t)i * DINNER * DSTATE, Dp + i * DINNER, pyh, pyl);

        // out_proj accumulate: x += y @ out_W^T  (fp16 hi/lo 2-pass)
        {
            const uint16_t* bw = (const uint16_t*)(pwo + (size_t)i * NEMBD * DINNER);
            dim3 g(LSEQ / 128, NEMBD / 128);
            gemm_mma4<true><<<g, 256, SMEM_G>>>(
                (const uint16_t*)pyh, (const uint16_t*)pyl, bw,
                2, px, NEMBD, DINNER, NEMBD);
        }
    }

    // final norm (fp16 out) + tied lm head (fp16 single pass)
    rmsnorm_out_kernel<1><<<LSEQ, 256>>>(px, normf_w, normf_b, phh, nullptr);
    {
        dim3 g(LSEQ / 128, (NVOCAB + 127) / 128);
        const uint16_t* ah = (const uint16_t*)phh;
        const uint16_t* bh = (const uint16_t*)pembh;
        gemm_mma4<false><<<g, 256, SMEM_G>>>(
            ah, ah, bh, 1, out, NVOCAB, NEMBD, NVOCAB);
    }
}

// round 15
// speedup vs baseline: 2.3858x; 1.1686x over previous
#include <cuda_runtime.h>
#include <cuda_bf16.h>
#include <cuda_fp16.h>
#include <math.h>
#include <stdint.h>

// ---------------------------------------------------------------------------
// Mamba forward, L=2048, 4 layers.
// Big GEMMs via mma.sync (HMMA fp16): CTA 128x128, BK=64, 3-stage cp.async,
// 4 warps x 64x64 warp tiles, 2 CTAs/SM. Layer GEMMs = fp16 act-hi/lo 2-pass,
// lm head = 1-pass. Scan + gate: exact R8 structure (separate kernels).
// softplus fused into dt GEMM epilogue.
// ---------------------------------------------------------------------------

#define LSEQ    2048
#define NEMBD   1024
#define DINNER  2048
#define DSTATE  16
#define DTRANK  64
#define DCONV   4
#define NVOCAB  50257
#define NLAYERS 4
#define XDBL_W  (DTRANK + 2 * DSTATE)   // 96

// ----------------------------- scratch (static) ----------------------------
__device__ __align__(16) float g_x    [LSEQ * NEMBD];
__device__ __align__(16) float g_xr   [LSEQ * 2 * DINNER];
__device__ __align__(16) float g_u    [LSEQ * DINNER];
__device__ __align__(16) float g_xdbl [LSEQ * XDBL_W];
__device__ __align__(16) float g_delta[LSEQ * DINNER];
__device__ __align__(16) float g_y    [LSEQ * DINNER];
__device__ __align__(16) float g_part [8 * LSEQ * XDBL_W];

__device__ __align__(16) __half g_hh [LSEQ * NEMBD];    // activations hi
__device__ __align__(16) __half g_hl [LSEQ * NEMBD];    // activations lo
__device__ __align__(16) __half g_yh [LSEQ * DINNER];
__device__ __align__(16) __half g_yl [LSEQ * DINNER];
__device__ __align__(16) __half g_wi [NLAYERS * 2 * DINNER * NEMBD];
__device__ __align__(16) __half g_wo [NLAYERS * NEMBD * DINNER];
__device__ __align__(16) __half g_embh[(size_t)NVOCAB * NEMBD];

// ----------------------------- MMA helpers ---------------------------------
__device__ __forceinline__ void ldm_x4(uint32_t* r, uint32_t a) {
    asm volatile("ldmatrix.sync.aligned.m8n8.x4.shared.b16 {%0,%1,%2,%3}, [%4];"
                 : "=r"(r[0]), "=r"(r[1]), "=r"(r[2]), "=r"(r[3]) : "r"(a));
}
__device__ __forceinline__ void mma_16816(float* c, const uint32_t* a, const uint32_t* b) {
    asm volatile("mma.sync.aligned.m16n8k16.row.col.f32.f16.f16.f32 "
        "{%0,%1,%2,%3}, {%4,%5,%6,%7}, {%8,%9}, {%0,%1,%2,%3};"
        : "+f"(c[0]), "+f"(c[1]), "+f"(c[2]), "+f"(c[3])
        : "r"(a[0]), "r"(a[1]), "r"(a[2]), "r"(a[3]), "r"(b[0]), "r"(b[1]));
}

#define CPASYNC16(dst, src, sz) \
    asm volatile("cp.async.cg.shared.global [%0], [%1], 16, %2;" \
                 :: "r"(dst), "l"(src), "r"(sz))

// ------------- HMMA NT GEMM: C[M,N] (+)= sum_p A_p B^T ---------------------
// CTA 128x128, BK=64, 3-stage cp.async, 4 warps (2Mx2N), warp tile 64x64,
// 128 threads, 2 CTAs/SM (smem 110.6KB, ~190 regs/thread, cap 256).
// A,B fp16 K-major; M%128==0, K%64==0, N guarded.
template <bool ACC>
__global__ __launch_bounds__(128, 2) void gemm_mma5(
    const uint16_t* __restrict__ A0, const uint16_t* __restrict__ A1,
    const uint16_t* __restrict__ B,
    int npass, float* __restrict__ C, int N, int K, int ldc) {
    extern __shared__ __align__(16) uint16_t sm[];
    constexpr int PITCH = 72;                // 64 halfs + 8 pad (144B rows)
    constexpr int ASTR = 128 * PITCH;
    constexpr int BSTR = 128 * PITCH;

    const int tid = threadIdx.x, lane = tid & 31, wid = tid >> 5;
    const int bm = blockIdx.x * 128, bn = blockIdx.y * 128;
    const int kc64 = K >> 6;
    const int NC = npass * kc64;

    const uint32_t smBase = (uint32_t)__cvta_generic_to_shared(sm);
    const int lrow = tid >> 3, lch = tid & 7;    // 16 rows x 8 chunks per pass

    const int arow = (lane & 7) + ((lane >> 3) & 1) * 8;
    const int akc  = lane >> 4;
    const int brow = (lane & 7) + ((lane >> 4) << 3);
    const int bkc  = (lane >> 3) & 1;
    const int wm = (wid & 1) * 64;
    const int wn = (wid >> 1) * 64;

    float acc[4][8][4];
    #pragma unroll
    for (int i = 0; i < 4; i++)
        #pragma unroll
        for (int j = 0; j < 8; j++)
            #pragma unroll
            for (int k = 0; k < 4; k++) acc[i][j][k] = 0.f;

#define ISSUE(st, c) do { \
    int _p = (c) / kc64, _k = (c) - _p * kc64; \
    const uint16_t* _Aw = (_p == 0) ? A0 : A1; \
    _Pragma("unroll") \
    for (int _it = 0; _it < 8; _it++) { \
        int _r = lrow + _it * 16; \
        const uint16_t* _ga = _Aw + (size_t)(bm + _r) * K + _k * 64 + lch * 8; \
        uint32_t _da = smBase + 2u * ((st) * ASTR + _r * PITCH + lch * 8); \
        CPASYNC16(_da, _ga, 16); \
    } \
    _Pragma("unroll") \
    for (int _it = 0; _it < 8; _it++) { \
        int _r = lrow + _it * 16; \
        int _gr = bn + _r; \
        const uint16_t* _gb = B + (size_t)((_gr < N) ? _gr : 0) * K + _k * 64 + lch * 8; \
        uint32_t _db = smBase + 2u * (3 * ASTR + (st) * BSTR + _r * PITCH + lch * 8); \
        CPASYNC16(_db, _gb, (_gr < N) ? 16 : 0); \
    } \
  } while (0)

#define COMPUTE(st) do { \
    uint32_t _ab = smBase + 2u * ((st) * ASTR); \
    uint32_t _bb = smBase + 2u * (3 * ASTR + (st) * BSTR); \
    _Pragma("unroll") \
    for (int kk = 0; kk < 4; kk++) { \
        uint32_t af[4][4], bf[4][4]; \
        _Pragma("unroll") \
        for (int mi = 0; mi < 4; mi++) \
            ldm_x4(af[mi], _ab + 2u * ((wm + mi * 16 + arow) * PITCH + (kk * 2 + akc) * 8)); \
        _Pragma("unroll") \
        for (int nb = 0; nb < 4; nb++) \
            ldm_x4(bf[nb], _bb + 2u * ((wn + nb * 16 + brow) * PITCH + (kk * 2 + bkc) * 8)); \
        _Pragma("unroll") \
        for (int mi = 0; mi < 4; mi++) \
            _Pragma("unroll") \
            for (int ni = 0; ni < 8; ni++) \
                mma_16816(acc[mi][ni], af[mi], &bf[ni >> 1][(ni & 1) * 2]); \
    } \
  } while (0)

    ISSUE(0, 0);
    asm volatile("cp.async.commit_group;" ::: "memory");
    ISSUE(1, 1);
    asm volatile("cp.async.commit_group;" ::: "memory");

    for (int c = 0; c < NC; c++) {
        asm volatile("cp.async.wait_group 1;" ::: "memory");
        __syncthreads();
        if (c + 2 < NC) ISSUE((c + 2) % 3, c + 2);
        asm volatile("cp.async.commit_group;" ::: "memory");
        COMPUTE(c % 3);
    }
#undef ISSUE
#undef COMPUTE

    // epilogue
    const int gid = lane >> 2, q2 = (lane & 3) * 2;
    #pragma unroll
    for (int mi = 0; mi < 4; mi++) {
        const size_t row0 = (size_t)(bm + wm + mi * 16 + gid);
        const size_t row1 = row0 + 8;
        #pragma unroll
        for (int ni = 0; ni < 8; ni++) {
            const int col = bn + wn + ni * 8 + q2;
            const float* cf = acc[mi][ni];
            if (col < N) {
                if (ACC) { C[row0 * ldc + col] += cf[0]; C[row1 * ldc + col] += cf[2]; }
                else     { C[row0 * ldc + col]  = cf[0]; C[row1 * ldc + col]  = cf[2]; }
            }
            if (col + 1 < N) {
                if (ACC) { C[row0 * ldc + col + 1] += cf[1]; C[row1 * ldc + col + 1] += cf[3]; }
                else     { C[row0 * ldc + col + 1]  = cf[1]; C[row1 * ldc + col + 1]  = cf[3]; }
            }
        }
    }
}

#define SMEM_G (3 * (128 + 128) * 72 * 2)   // 110592 B

// ----------------------------- small helpers -------------------------------
__device__ __forceinline__ float sigm(float x) { return 1.0f / (1.0f + expf(-x)); }
__device__ __forceinline__ uint32_t packh2(float a, float b) {
    return (uint32_t)__half_as_ushort(__float2half_rn(a)) |
           ((uint32_t)__half_as_ushort(__float2half_rn(b)) << 16);
}
__device__ __forceinline__ void split2h(float a, float b, uint32_t& hi, uint32_t& lo) {
    __half ha = __float2half_rn(a), hb = __float2half_rn(b);
    float la = a - __half2float(ha), lb = b - __half2float(hb);
    hi = (uint32_t)__half_as_ushort(ha) | ((uint32_t)__half_as_ushort(hb) << 16);
    lo = packh2(la, lb);
}

// ----------------------------- conversions ---------------------------------
__global__ void convert_half_kernel(const float* __restrict__ src,
                                    __half* __restrict__ dst, int n4) {
    int i = blockIdx.x * blockDim.x + threadIdx.x;
    if (i >= n4) return;
    float4 v = reinterpret_cast<const float4*>(src)[i];
    uint2 o;
    o.x = packh2(v.x, v.y);
    o.y = packh2(v.z, v.w);
    reinterpret_cast<uint2*>(dst)[i] = o;
}

// ----------------------------- embedding gather ----------------------------
__global__ void embed_kernel(const int* __restrict__ tokens,
                             const float* __restrict__ emb,
                             float* __restrict__ x) {
    int l = blockIdx.x;
    int tok = tokens[l];
    const float4* src = reinterpret_cast<const float4*>(emb + (size_t)tok * NEMBD);
    float4* dst = reinterpret_cast<float4*>(x + (size_t)l * NEMBD);
    dst[threadIdx.x] = src[threadIdx.x];
}

// ---------------- rmsnorm (width 1024) with fp16 outputs -------------------
template <int OUT_MODE>   // 0: fp16 hi/lo; 1: fp16 single
__global__ void rmsnorm_out_kernel(const float* __restrict__ x,
                                   const float* __restrict__ w,
                                   const float* __restrict__ b,
                                   void* __restrict__ out_hi,
                                   void* __restrict__ out_lo) {
    int l = blockIdx.x;
    const float4* xr = reinterpret_cast<const float4*>(x + (size_t)l * NEMBD);
    float4 v = xr[threadIdx.x];
    float ss = v.x * v.x + v.y * v.y + v.z * v.z + v.w * v.w;
    #pragma unroll
    for (int o = 16; o > 0; o >>= 1) ss += __shfl_xor_sync(0xffffffffu, ss, o);
    __shared__ float wsum[8];
    __shared__ float inv_s;
    if ((threadIdx.x & 31) == 0) wsum[threadIdx.x >> 5] = ss;
    __syncthreads();
    if (threadIdx.x == 0) {
        float t = 0.f;
        #pragma unroll
        for (int k = 0; k < 8; k++) t += wsum[k];
        inv_s = rsqrtf(t / (float)NEMBD + 1e-6f);
    }
    __syncthreads();
    float inv = inv_s;
    float4 wv = reinterpret_cast<const float4*>(w)[threadIdx.x];
    float4 bv = reinterpret_cast<const float4*>(b)[threadIdx.x];
    float o0 = v.x * inv * wv.x + bv.x;
    float o1 = v.y * inv * wv.y + bv.y;
    float o2 = v.z * inv * wv.z + bv.z;
    float o3 = v.w * inv * wv.w + bv.w;
    size_t base = (size_t)l * NEMBD / 4 + threadIdx.x;
    if (OUT_MODE == 0) {
        uint2 h, lo;
        split2h(o0, o1, h.x, lo.x);
        split2h(o2, o3, h.y, lo.y);
        reinterpret_cast<uint2*>(out_hi)[base] = h;
        reinterpret_cast<uint2*>(out_lo)[base] = lo;
    } else {
        uint2 o;
        o.x = packh2(o0, o1);
        o.y = packh2(o2, o3);
        reinterpret_cast<uint2*>(out_hi)[base] = o;
    }
}

// ------------------- fp32 tiled NT GEMM (small GEMMs) ----------------------
// SOFTP: epilogue computes softplus(acc + bias[col]) (dt-proj fusion).
template <bool ACC, bool SPLIT, bool SOFTP>
__global__ __launch_bounds__(256) void gemm_nt(
    const float* __restrict__ A, const float* __restrict__ B,
    float* __restrict__ C, int M, int N, int K,
    int lda, int ldb, int ldc, int kchunk, long long cstride,
    const float* __restrict__ bias) {
    __shared__ float As[16][128 + 4];
    __shared__ float Bs[16][128 + 4];

    int k_begin = 0, k_end = K;
    if (SPLIT) {
        k_begin = blockIdx.z * kchunk;
        k_end = min(K, k_begin + kchunk);
        C += (long long)blockIdx.z * cstride;
    }
    const int bm = blockIdx.y * 128;
    const int bn = blockIdx.x * 128;
    const int tid = threadIdx.x;
    const int tx = tid & 15;
    const int ty = tid >> 4;

    float acc[8][8];
    #pragma unroll
    for (int i = 0; i < 8; i++)
        #pragma unroll
        for (int j = 0; j < 8; j++) acc[i][j] = 0.f;

    for (int k0 = k_begin; k0 < k_end; k0 += 16) {
        #pragma unroll
        for (int s = 0; s < 2; ++s) {
            int idx = tid + s * 256;
            int row = idx >> 2;
            int k4 = (idx & 3) * 4;
            float4 va = *reinterpret_cast<const float4*>(
                &A[(size_t)(bm + row) * lda + k0 + k4]);
            As[k4 + 0][row] = va.x; As[k4 + 1][row] = va.y;
            As[k4 + 2][row] = va.z; As[k4 + 3][row] = va.w;
            float4 vb;
            if (bn + row < N)
                vb = *reinterpret_cast<const float4*>(
                    &B[(size_t)(bn + row) * ldb + k0 + k4]);
            else
                vb = make_float4(0.f, 0.f, 0.f, 0.f);
            Bs[k4 + 0][row] = vb.x; Bs[k4 + 1][row] = vb.y;
            Bs[k4 + 2][row] = vb.z; Bs[k4 + 3][row] = vb.w;
        }
        __syncthreads();
        #pragma unroll
        for (int kk = 0; kk < 16; ++kk) {
            float a[8], b[8];
            *reinterpret_cast<float4*>(&a[0]) =
                *reinterpret_cast<const float4*>(&As[kk][ty * 4]);
            *reinterpret_cast<float4*>(&a[4]) =
                *reinterpret_cast<const float4*>(&As[kk][64 + ty * 4]);
            *reinterpret_cast<float4*>(&b[0]) =
                *reinterpret_cast<const float4*>(&Bs[kk][tx * 4]);
            *reinterpret_cast<float4*>(&b[4]) =
                *reinterpret_cast<const float4*>(&Bs[kk][64 + tx * 4]);
            #pragma unroll
            for (int i = 0; i < 8; i++)
                #pragma unroll
                for (int j = 0; j < 8; j++)
                    acc[i][j] = fmaf(a[i], b[j], acc[i][j]);
        }
        __syncthreads();
    }

    #pragma unroll
    for (int i = 0; i < 8; i++) {
        int ri = bm + ((i < 4) ? (ty * 4 + i) : (64 + ty * 4 + (i - 4)));
        #pragma unroll
        for (int j = 0; j < 8; j++) {
            int cj = bn + ((j < 4) ? (tx * 4 + j) : (64 + tx * 4 + (j - 4)));
            if (cj < N) {
                size_t off = (size_t)ri * ldc + cj;
                float v = acc[i][j];
                if (SOFTP) {
                    float t = v + bias[cj];
                    v = fmaxf(t, 0.f) + log1pf(expf(-fabsf(t)));
                }
                if (ACC) C[off] += v;
                else     C[off]  = v;
            }
        }
    }
}

__global__ void reduce_split_kernel(const float* __restrict__ part,
                                    float* __restrict__ out,
                                    int n, int nz, long long stride) {
    int i = blockIdx.x * blockDim.x + threadIdx.x;
    if (i < n) {
        float s = 0.f;
        for (int z = 0; z < nz; z++) s += part[(long long)z * stride + i];
        out[i] = s;
    }
}

// --------------------- depthwise causal conv + silu ------------------------
__global__ void conv_silu_kernel(const float* __restrict__ xr,
                                 const float* __restrict__ W,
                                 const float* __restrict__ b,
                                 float* __restrict__ u) {
    int idx = blockIdx.x * blockDim.x + threadIdx.x;
    int d = idx & (DINNER - 1);
    int l = idx >> 11;
    float acc = b[d];
    #pragma unroll
    for (int j = 0; j < DCONV; j++) {
        int t = l - (DCONV - 1) + j;
        if (t >= 0) acc = fmaf(xr[(size_t)t * (2 * DINNER) + d], W[d * DCONV + j], acc);
    }
    u[(size_t)l * DINNER + d] = acc * sigm(acc);
}

// --------------------------- selective scan (R8 form) ----------------------
#define TCHUNK 64
__global__ __launch_bounds__(256) void scan_kernel(
    const float* __restrict__ delta, const float* __restrict__ u,
    const float* __restrict__ xdbl,
    const float* __restrict__ A_log, const float* __restrict__ Dp,
    float* __restrict__ y) {
    const int lane_n = threadIdx.x & 15;
    const int ch_loc = threadIdx.x >> 4;
    const int d = blockIdx.x * 16 + ch_loc;
    const float Aneg = -expf(A_log[(size_t)d * DSTATE + lane_n]);
    const float Dval = Dp[d];
    float s = 0.f;

    __shared__ float Bsh[TCHUNK][16];
    __shared__ float Csh[TCHUNK][16];
    __shared__ float dsh[TCHUNK][16];
    __shared__ float ush[TCHUNK][16];

    for (int t0 = 0; t0 < LSEQ; t0 += TCHUNK) {
        __syncthreads();
        for (int i = threadIdx.x; i < TCHUNK * 16; i += 256) {
            int tt = i >> 4, n = i & 15;
            size_t trow = (size_t)(t0 + tt);
            Bsh[tt][n] = xdbl[trow * XDBL_W + DTRANK + n];
            Csh[tt][n] = xdbl[trow * XDBL_W + DTRANK + DSTATE + n];
            dsh[tt][n] = delta[trow * DINNER + blockIdx.x * 16 + n];
            ush[tt][n] = u    [trow * DINNER + blockIdx.x * 16 + n];
        }
        __syncthreads();
        #pragma unroll 4
        for (int tt = 0; tt < TCHUNK; ++tt) {
            float dt = dsh[tt][ch_loc];
            float uu = ush[tt][ch_loc];
            float dA = __expf(dt * Aneg);
            float dBu = dt * uu * Bsh[tt][lane_n];
            s = fmaf(dA, s, dBu);
            float yv = s * Csh[tt][lane_n];
            yv += __shfl_xor_sync(0xffffffffu, yv, 8);
            yv += __shfl_xor_sync(0xffffffffu, yv, 4);
            yv += __shfl_xor_sync(0xffffffffu, yv, 2);
            yv += __shfl_xor_sync(0xffffffffu, yv, 1);
            if (lane_n == 0)
                y[(size_t)(t0 + tt) * DINNER + d] = yv + Dval * uu;
        }
    }
}

// ------------------- silu gate + fp16 hi/lo split (R8 form) ----------------
__global__ void gate_split_kernel(const float* __restrict__ y,
                                  const float* __restrict__ xr,
                                  __half* __restrict__ yh,
                                  __half* __restrict__ yl) {
    int i = blockIdx.x * blockDim.x + threadIdx.x;    // over L*DINNER/4
    int base = i * 4;
    int l = base >> 11;
    int d = base & (DINNER - 1);
    float4 yv = reinterpret_cast<const float4*>(y)[i];
    float4 rv = *reinterpret_cast<const float4*>(
        xr + (size_t)l * (2 * DINNER) + DINNER + d);
    float g0 = yv.x * (rv.x * sigm(rv.x));
    float g1 = yv.y * (rv.y * sigm(rv.y));
    float g2 = yv.z * (rv.z * sigm(rv.z));
    float g3 = yv.w * (rv.w * sigm(rv.w));
    uint2 h, lo;
    split2h(g0, g1, h.x, lo.x);
    split2h(g2, g3, h.y, lo.y);
    reinterpret_cast<uint2*>(yh)[i] = h;
    reinterpret_cast<uint2*>(yl)[i] = lo;
}

// ------------------------------- launcher ----------------------------------
extern "C" void kernel_launch(void* const* d_in, const int* in_sizes, int n_in,
                              void* d_out, int out_size) {
    const int*   tokens    = (const int*)  d_in[0];
    const float* emb_W     = (const float*)d_in[1];
    const float* in_proj_W = (const float*)d_in[2];
    const float* conv_W    = (const float*)d_in[3];
    const float* conv_b    = (const float*)d_in[4];
    const float* xproj_W   = (const float*)d_in[5];
    const float* dt_W      = (const float*)d_in[6];
    const float* dt_b      = (const float*)d_in[7];
    const float* A_log     = (const float*)d_in[8];
    const float* Dp        = (const float*)d_in[9];
    const float* out_W     = (const float*)d_in[10];
    const float* rms_w     = (const float*)d_in[11];
    const float* rms_b     = (const float*)d_in[12];
    const float* normf_w   = (const float*)d_in[13];
    const float* normf_b   = (const float*)d_in[14];
    float* out = (float*)d_out;

    float *px, *pxr, *pu, *pxdbl, *pdelta, *py, *ppart;
    __half *phh, *phl, *pyh, *pyl, *pwi, *pwo, *pembh;
    cudaGetSymbolAddress((void**)&px,     g_x);
    cudaGetSymbolAddress((void**)&pxr,    g_xr);
    cudaGetSymbolAddress((void**)&pu,     g_u);
    cudaGetSymbolAddress((void**)&pxdbl,  g_xdbl);
    cudaGetSymbolAddress((void**)&pdelta, g_delta);
    cudaGetSymbolAddress((void**)&py,     g_y);
    cudaGetSymbolAddress((void**)&ppart,  g_part);
    cudaGetSymbolAddress((void**)&phh,    g_hh);
    cudaGetSymbolAddress((void**)&phl,    g_hl);
    cudaGetSymbolAddress((void**)&pyh,    g_yh);
    cudaGetSymbolAddress((void**)&pyl,    g_yl);
    cudaGetSymbolAddress((void**)&pwi,    g_wi);
    cudaGetSymbolAddress((void**)&pwo,    g_wo);
    cudaGetSymbolAddress((void**)&pembh,  g_embh);

    cudaFuncSetAttribute(gemm_mma5<false>,
        cudaFuncAttributeMaxDynamicSharedMemorySize, SMEM_G);
    cudaFuncSetAttribute(gemm_mma5<true>,
        cudaFuncAttributeMaxDynamicSharedMemorySize, SMEM_G);

    // ---- weight conversions to fp16 (every launch; deterministic) ----
    {
        int n4 = NLAYERS * 2 * DINNER * NEMBD / 4;
        convert_half_kernel<<<(n4 + 255) / 256, 256>>>(in_proj_W, pwi, n4);
        n4 = NLAYERS * NEMBD * DINNER / 4;
        convert_half_kernel<<<(n4 + 255) / 256, 256>>>(out_W, pwo, n4);
        n4 = (int)((size_t)NVOCAB * NEMBD / 4);
        convert_half_kernel<<<(n4 + 255) / 256, 256>>>(emb_W, pembh, n4);
    }

    embed_kernel<<<LSEQ, 256>>>(tokens, emb_W, px);

    for (int i = 0; i < NLAYERS; i++) {
        rmsnorm_out_kernel<0><<<LSEQ, 256>>>(px, rms_w + i * NEMBD,
                                             rms_b + i * NEMBD, phh, phl);

        // in_proj: xr[L,4096] = h @ W^T  (fp16 hi/lo 2-pass)
        {
            const uint16_t* bw = (const uint16_t*)(pwi + (size_t)i * 2 * DINNER * NEMBD);
            dim3 g(LSEQ / 128, 2 * DINNER / 128);
            gemm_mma5<false><<<g, 128, SMEM_G>>>(
                (const uint16_t*)phh, (const uint16_t*)phl, bw,
                2, pxr, 2 * DINNER, NEMBD, 2 * DINNER);
        }

        conv_silu_kernel<<<LSEQ * DINNER / 256, 256>>>(
            pxr, conv_W + (size_t)i * DINNER * DCONV, conv_b + i * DINNER, pu);

        // x_proj (N=96): split-K fp32
        {
            dim3 grid(1, LSEQ / 128, 8);
            gemm_nt<false, true, false><<<grid, 256>>>(
                pu, xproj_W + (size_t)i * XDBL_W * DINNER, ppart,
                LSEQ, XDBL_W, DINNER, DINNER, DINNER, XDBL_W,
                DINNER / 8, (long long)LSEQ * XDBL_W, nullptr);
            int n = LSEQ * XDBL_W;
            reduce_split_kernel<<<(n + 255) / 256, 256>>>(
                ppart, pxdbl, n, 8, (long long)LSEQ * XDBL_W);
        }

        // dt proj + fused softplus
        {
            dim3 grid(DINNER / 128, LSEQ / 128);
            gemm_nt<false, false, true><<<grid, 256>>>(
                pxdbl, dt_W + (size_t)i * DINNER * DTRANK, pdelta,
                LSEQ, DINNER, DTRANK, XDBL_W, DTRANK, DINNER, 0, 0,
                dt_b + i * DINNER);
        }

        // scan (R8 form)
        scan_kernel<<<DINNER / 16, 256>>>(
            pdelta, pu, pxdbl,
            A_log + (size_t)i * DINNER * DSTATE, Dp + i * DINNER, py);

        // gate + fp16 split (R8 form)
        gate_split_kernel<<<LSEQ * DINNER / 4 / 256, 256>>>(py, pxr, pyh, pyl);

        // out_proj accumulate: x += y @ out_W^T  (fp16 hi/lo 2-pass)
        {
            const uint16_t* bw = (const uint16_t*)(pwo + (size_t)i * NEMBD * DINNER);
            dim3 g(LSEQ / 128, NEMBD / 128);
            gemm_mma5<true><<<g, 128, SMEM_G>>>(
                (const uint16_t*)pyh, (const uint16_t*)pyl, bw,
                2, px, NEMBD, DINNER, NEMBD);
        }
    }

    // final norm (fp16 out) + tied lm head (fp16 single pass)
    rmsnorm_out_kernel<1><<<LSEQ, 256>>>(px, normf_w, normf_b, phh, nullptr);
    {
        dim3 g(LSEQ / 128, (NVOCAB + 127) / 128);
        const uint16_t* ah = (const uint16_t*)phh;
        const uint16_t* bh = (const uint16_t*)pembh;
        gemm_mma5<false><<<g, 128, SMEM_G>>>(
            ah, ah, bh, 1, out, NVOCAB, NEMBD, NVOCAB);
    }
}

// round 16
// speedup vs baseline: 2.9449x; 1.2344x over previous
#include <cuda_runtime.h>
#include <cuda_bf16.h>
#include <cuda_fp16.h>
#include <math.h>
#include <stdint.h>

// ---------------------------------------------------------------------------
// Mamba forward, L=2048, 4 layers.
// Big GEMMs via mma.sync (HMMA fp16), CTA 128x128, BK=64, 3-stage cp.async,
// 8 warps, 2 CTAs/SM (R8 config, pipe-saturated ~92 TFMA/s).
// Layer GEMMs = fp16 act-hi/lo 2-pass, lm head = 1-pass.
// Scan: chunk-parallel (P=8): scanA chunk transfer fns -> scanB carry
// composition -> scanC re-scan with corrected s0. Gate separate (R8 law:
// keep the serial loop minimal). softplus fused into dt GEMM epilogue.
// ---------------------------------------------------------------------------

#define LSEQ    2048
#define NEMBD   1024
#define DINNER  2048
#define DSTATE  16
#define DTRANK  64
#define DCONV   4
#define NVOCAB  50257
#define NLAYERS 4
#define XDBL_W  (DTRANK + 2 * DSTATE)   // 96
#define PCHUNK  8
#define CLEN    (LSEQ / PCHUNK)         // 256

// ----------------------------- scratch (static) ----------------------------
__device__ __align__(16) float g_x    [LSEQ * NEMBD];
__device__ __align__(16) float g_xr   [LSEQ * 2 * DINNER];
__device__ __align__(16) float g_u    [LSEQ * DINNER];
__device__ __align__(16) float g_xdbl [LSEQ * XDBL_W];
__device__ __align__(16) float g_delta[LSEQ * DINNER];
__device__ __align__(16) float g_y    [LSEQ * DINNER];
__device__ __align__(16) float g_part [8 * LSEQ * XDBL_W];
__device__ __align__(16) float g_cA   [PCHUNK * DINNER * DSTATE];
__device__ __align__(16) float g_cS   [PCHUNK * DINNER * DSTATE];
__device__ __align__(16) float g_s0   [PCHUNK * DINNER * DSTATE];

__device__ __align__(16) __half g_hh [LSEQ * NEMBD];    // activations hi
__device__ __align__(16) __half g_hl [LSEQ * NEMBD];    // activations lo
__device__ __align__(16) __half g_yh [LSEQ * DINNER];
__device__ __align__(16) __half g_yl [LSEQ * DINNER];
__device__ __align__(16) __half g_wi [NLAYERS * 2 * DINNER * NEMBD];
__device__ __align__(16) __half g_wo [NLAYERS * NEMBD * DINNER];
__device__ __align__(16) __half g_embh[(size_t)NVOCAB * NEMBD];

// ----------------------------- MMA helpers ---------------------------------
__device__ __forceinline__ void ldm_x4(uint32_t* r, uint32_t a) {
    asm volatile("ldmatrix.sync.aligned.m8n8.x4.shared.b16 {%0,%1,%2,%3}, [%4];"
                 : "=r"(r[0]), "=r"(r[1]), "=r"(r[2]), "=r"(r[3]) : "r"(a));
}
__device__ __forceinline__ void mma_16816(float* c, const uint32_t* a, const uint32_t* b) {
    asm volatile("mma.sync.aligned.m16n8k16.row.col.f32.f16.f16.f32 "
        "{%0,%1,%2,%3}, {%4,%5,%6,%7}, {%8,%9}, {%0,%1,%2,%3};"
        : "+f"(c[0]), "+f"(c[1]), "+f"(c[2]), "+f"(c[3])
        : "r"(a[0]), "r"(a[1]), "r"(a[2]), "r"(a[3]), "r"(b[0]), "r"(b[1]));
}

#define CPASYNC16(dst, src, sz) \
    asm volatile("cp.async.cg.shared.global [%0], [%1], 16, %2;" \
                 :: "r"(dst), "l"(src), "r"(sz))

// ------------- HMMA NT GEMM: C[M,N] (+)= sum_p A_p B^T ---------------------
// (R8 config — benched 2974us; do not grow the COMPUTE body: reg budget 128.)
template <bool ACC>
__global__ __launch_bounds__(256, 2) void gemm_mma4(
    const uint16_t* __restrict__ A0, const uint16_t* __restrict__ A1,
    const uint16_t* __restrict__ B,
    int npass, float* __restrict__ C, int N, int K, int ldc) {
    extern __shared__ __align__(16) uint16_t sm[];
    constexpr int PITCH = 72;
    constexpr int ASTR = 128 * PITCH;
    constexpr int BSTR = 128 * PITCH;

    const int tid = threadIdx.x, lane = tid & 31, wid = tid >> 5;
    const int bm = blockIdx.x * 128, bn = blockIdx.y * 128;
    const int kc64 = K >> 6;
    const int NC = npass * kc64;

    const uint32_t smBase = (uint32_t)__cvta_generic_to_shared(sm);
    const int lrow = tid >> 3, lch = tid & 7;

    const int arow = (lane & 7) + ((lane >> 3) & 1) * 8;
    const int akc  = lane >> 4;
    const int brow = (lane & 7) + ((lane >> 4) << 3);
    const int bkc  = (lane >> 3) & 1;
    const int wm = (wid & 1) * 64;
    const int wn = (wid >> 1) * 32;

    float acc[4][4][4];
    #pragma unroll
    for (int i = 0; i < 4; i++)
        #pragma unroll
        for (int j = 0; j < 4; j++)
            #pragma unroll
            for (int k = 0; k < 4; k++) acc[i][j][k] = 0.f;

#define ISSUE(st, c) do { \
    int _p = (c) / kc64, _k = (c) - _p * kc64; \
    const uint16_t* _Aw = (_p == 0) ? A0 : A1; \
    _Pragma("unroll") \
    for (int _it = 0; _it < 4; _it++) { \
        int _r = lrow + _it * 32; \
        const uint16_t* _ga = _Aw + (size_t)(bm + _r) * K + _k * 64 + lch * 8; \
        uint32_t _da = smBase + 2u * ((st) * ASTR + _r * PITCH + lch * 8); \
        CPASYNC16(_da, _ga, 16); \
    } \
    _Pragma("unroll") \
    for (int _it = 0; _it < 4; _it++) { \
        int _r = lrow + _it * 32; \
        int _gr = bn + _r; \
        const uint16_t* _gb = B + (size_t)((_gr < N) ? _gr : 0) * K + _k * 64 + lch * 8; \
        uint32_t _db = smBase + 2u * (3 * ASTR + (st) * BSTR + _r * PITCH + lch * 8); \
        CPASYNC16(_db, _gb, (_gr < N) ? 16 : 0); \
    } \
  } while (0)

#define COMPUTE(st) do { \
    uint32_t _ab = smBase + 2u * ((st) * ASTR); \
    uint32_t _bb = smBase + 2u * (3 * ASTR + (st) * BSTR); \
    _Pragma("unroll") \
    for (int kk = 0; kk < 4; kk++) { \
        uint32_t af[4][4], bf[2][4]; \
        _Pragma("unroll") \
        for (int mi = 0; mi < 4; mi++) \
            ldm_x4(af[mi], _ab + 2u * ((wm + mi * 16 + arow) * PITCH + (kk * 2 + akc) * 8)); \
        _Pragma("unroll") \
        for (int nb = 0; nb < 2; nb++) \
            ldm_x4(bf[nb], _bb + 2u * ((wn + nb * 16 + brow) * PITCH + (kk * 2 + bkc) * 8)); \
        _Pragma("unroll") \
        for (int mi = 0; mi < 4; mi++) \
            _Pragma("unroll") \
            for (int ni = 0; ni < 4; ni++) \
                mma_16816(acc[mi][ni], af[mi], &bf[ni >> 1][(ni & 1) * 2]); \
    } \
  } while (0)

    ISSUE(0, 0);
    asm volatile("cp.async.commit_group;" ::: "memory");
    ISSUE(1, 1);
    asm volatile("cp.async.commit_group;" ::: "memory");

    for (int c = 0; c < NC; c++) {
        asm volatile("cp.async.wait_group 1;" ::: "memory");
        __syncthreads();
        if (c + 2 < NC) ISSUE((c + 2) % 3, c + 2);
        asm volatile("cp.async.commit_group;" ::: "memory");
        COMPUTE(c % 3);
    }
#undef ISSUE
#undef COMPUTE

    const int gid = lane >> 2, q2 = (lane & 3) * 2;
    #pragma unroll
    for (int mi = 0; mi < 4; mi++) {
        const size_t row0 = (size_t)(bm + wm + mi * 16 + gid);
        const size_t row1 = row0 + 8;
        #pragma unroll
        for (int ni = 0; ni < 4; ni++) {
            const int col = bn + wn + ni * 8 + q2;
            const float* cf = acc[mi][ni];
            if (col < N) {
                if (ACC) { C[row0 * ldc + col] += cf[0]; C[row1 * ldc + col] += cf[2]; }
                else     { C[row0 * ldc + col]  = cf[0]; C[row1 * ldc + col]  = cf[2]; }
            }
            if (col + 1 < N) {
                if (ACC) { C[row0 * ldc + col + 1] += cf[1]; C[row1 * ldc + col + 1] += cf[3]; }
                else     { C[row0 * ldc + col + 1]  = cf[1]; C[row1 * ldc + col + 1]  = cf[3]; }
            }
        }
    }
}

#define SMEM_G (3 * (128 + 128) * 72 * 2)   // 110592 B

// ----------------------------- small helpers -------------------------------
__device__ __forceinline__ float sigm(float x) { return 1.0f / (1.0f + expf(-x)); }
__device__ __forceinline__ uint32_t packh2(float a, float b) {
    return (uint32_t)__half_as_ushort(__float2half_rn(a)) |
           ((uint32_t)__half_as_ushort(__float2half_rn(b)) << 16);
}
__device__ __forceinline__ void split2h(float a, float b, uint32_t& hi, uint32_t& lo) {
    __half ha = __float2half_rn(a), hb = __float2half_rn(b);
    float la = a - __half2float(ha), lb = b - __half2float(hb);
    hi = (uint32_t)__half_as_ushort(ha) | ((uint32_t)__half_as_ushort(hb) << 16);
    lo = packh2(la, lb);
}

// ----------------------------- conversions ---------------------------------
__global__ void convert_half_kernel(const float* __restrict__ src,
                                    __half* __restrict__ dst, int n4) {
    int i = blockIdx.x * blockDim.x + threadIdx.x;
    if (i >= n4) return;
    float4 v = reinterpret_cast<const float4*>(src)[i];
    uint2 o;
    o.x = packh2(v.x, v.y);
    o.y = packh2(v.z, v.w);
    reinterpret_cast<uint2*>(dst)[i] = o;
}

// ----------------------------- embedding gather ----------------------------
__global__ void embed_kernel(const int* __restrict__ tokens,
                             const float* __restrict__ emb,
                             float* __restrict__ x) {
    int l = blockIdx.x;
    int tok = tokens[l];
    const float4* src = reinterpret_cast<const float4*>(emb + (size_t)tok * NEMBD);
    float4* dst = reinterpret_cast<float4*>(x + (size_t)l * NEMBD);
    dst[threadIdx.x] = src[threadIdx.x];
}

// ---------------- rmsnorm (width 1024) with fp16 outputs -------------------
template <int OUT_MODE>
__global__ void rmsnorm_out_kernel(const float* __restrict__ x,
                                   const float* __restrict__ w,
                                   const float* __restrict__ b,
                                   void* __restrict__ out_hi,
                                   void* __restrict__ out_lo) {
    int l = blockIdx.x;
    const float4* xr = reinterpret_cast<const float4*>(x + (size_t)l * NEMBD);
    float4 v = xr[threadIdx.x];
    float ss = v.x * v.x + v.y * v.y + v.z * v.z + v.w * v.w;
    #pragma unroll
    for (int o = 16; o > 0; o >>= 1) ss += __shfl_xor_sync(0xffffffffu, ss, o);
    __shared__ float wsum[8];
    __shared__ float inv_s;
    if ((threadIdx.x & 31) == 0) wsum[threadIdx.x >> 5] = ss;
    __syncthreads();
    if (threadIdx.x == 0) {
        float t = 0.f;
        #pragma unroll
        for (int k = 0; k < 8; k++) t += wsum[k];
        inv_s = rsqrtf(t / (float)NEMBD + 1e-6f);
    }
    __syncthreads();
    float inv = inv_s;
    float4 wv = reinterpret_cast<const float4*>(w)[threadIdx.x];
    float4 bv = reinterpret_cast<const float4*>(b)[threadIdx.x];
    float o0 = v.x * inv * wv.x + bv.x;
    float o1 = v.y * inv * wv.y + bv.y;
    float o2 = v.z * inv * wv.z + bv.z;
    float o3 = v.w * inv * wv.w + bv.w;
    size_t base = (size_t)l * NEMBD / 4 + threadIdx.x;
    if (OUT_MODE == 0) {
        uint2 h, lo;
        split2h(o0, o1, h.x, lo.x);
        split2h(o2, o3, h.y, lo.y);
        reinterpret_cast<uint2*>(out_hi)[base] = h;
        reinterpret_cast<uint2*>(out_lo)[base] = lo;
    } else {
        uint2 o;
        o.x = packh2(o0, o1);
        o.y = packh2(o2, o3);
        reinterpret_cast<uint2*>(out_hi)[base] = o;
    }
}

// ------------------- fp32 tiled NT GEMM (small GEMMs) ----------------------
template <bool ACC, bool SPLIT, bool SOFTP>
__global__ __launch_bounds__(256) void gemm_nt(
    const float* __restrict__ A, const float* __restrict__ B,
    float* __restrict__ C, int M, int N, int K,
    int lda, int ldb, int ldc, int kchunk, long long cstride,
    const float* __restrict__ bias) {
    __shared__ float As[16][128 + 4];
    __shared__ float Bs[16][128 + 4];

    int k_begin = 0, k_end = K;
    if (SPLIT) {
        k_begin = blockIdx.z * kchunk;
        k_end = min(K, k_begin + kchunk);
        C += (long long)blockIdx.z * cstride;
    }
    const int bm = blockIdx.y * 128;
    const int bn = blockIdx.x * 128;
    const int tid = threadIdx.x;
    const int tx = tid & 15;
    const int ty = tid >> 4;

    float acc[8][8];
    #pragma unroll
    for (int i = 0; i < 8; i++)
        #pragma unroll
        for (int j = 0; j < 8; j++) acc[i][j] = 0.f;

    for (int k0 = k_begin; k0 < k_end; k0 += 16) {
        #pragma unroll
        for (int s = 0; s < 2; ++s) {
            int idx = tid + s * 256;
            int row = idx >> 2;
            int k4 = (idx & 3) * 4;
            float4 va = *reinterpret_cast<const float4*>(
                &A[(size_t)(bm + row) * lda + k0 + k4]);
            As[k4 + 0][row] = va.x; As[k4 + 1][row] = va.y;
            As[k4 + 2][row] = va.z; As[k4 + 3][row] = va.w;
            float4 vb;
            if (bn + row < N)
                vb = *reinterpret_cast<const float4*>(
                    &B[(size_t)(bn + row) * ldb + k0 + k4]);
            else
                vb = make_float4(0.f, 0.f, 0.f, 0.f);
            Bs[k4 + 0][row] = vb.x; Bs[k4 + 1][row] = vb.y;
            Bs[k4 + 2][row] = vb.z; Bs[k4 + 3][row] = vb.w;
        }
        __syncthreads();
        #pragma unroll
        for (int kk = 0; kk < 16; ++kk) {
            float a[8], b[8];
            *reinterpret_cast<float4*>(&a[0]) =
                *reinterpret_cast<const float4*>(&As[kk][ty * 4]);
            *reinterpret_cast<float4*>(&a[4]) =
                *reinterpret_cast<const float4*>(&As[kk][64 + ty * 4]);
            *reinterpret_cast<float4*>(&b[0]) =
                *reinterpret_cast<const float4*>(&Bs[kk][tx * 4]);
            *reinterpret_cast<float4*>(&b[4]) =
                *reinterpret_cast<const float4*>(&Bs[kk][64 + tx * 4]);
            #pragma unroll
            for (int i = 0; i < 8; i++)
                #pragma unroll
                for (int j = 0; j < 8; j++)
                    acc[i][j] = fmaf(a[i], b[j], acc[i][j]);
        }
        __syncthreads();
    }

    #pragma unroll
    for (int i = 0; i < 8; i++) {
        int ri = bm + ((i < 4) ? (ty * 4 + i) : (64 + ty * 4 + (i - 4)));
        #pragma unroll
        for (int j = 0; j < 8; j++) {
            int cj = bn + ((j < 4) ? (tx * 4 + j) : (64 + tx * 4 + (j - 4)));
            if (cj < N) {
                size_t off = (size_t)ri * ldc + cj;
                float v = acc[i][j];
                if (SOFTP) {
                    float t = v + bias[cj];
                    v = fmaxf(t, 0.f) + log1pf(expf(-fabsf(t)));
                }
                if (ACC) C[off] += v;
                else     C[off]  = v;
            }
        }
    }
}

__global__ void reduce_split_kernel(const float* __restrict__ part,
                                    float* __restrict__ out,
                                    int n, int nz, long long stride) {
    int i = blockIdx.x * blockDim.x + threadIdx.x;
    if (i < n) {
        float s = 0.f;
        for (int z = 0; z < nz; z++) s += part[(long long)z * stride + i];
        out[i] = s;
    }
}

// --------------- depthwise causal conv + silu (float4) ---------------------
__global__ void conv_silu_kernel(const float* __restrict__ xr,
                                 const float* __restrict__ W,
                                 const float* __restrict__ b,
                                 float* __restrict__ u) {
    int i = blockIdx.x * blockDim.x + threadIdx.x;   // over L*DINNER/4
    int d = (i * 4) & (DINNER - 1);
    int l = (i * 4) >> 11;
    float4 bb = *reinterpret_cast<const float4*>(&b[d]);
    float a0 = bb.x, a1 = bb.y, a2 = bb.z, a3 = bb.w;
    float4 w0 = *reinterpret_cast<const float4*>(&W[(d + 0) * 4]);
    float4 w1 = *reinterpret_cast<const float4*>(&W[(d + 1) * 4]);
    float4 w2 = *reinterpret_cast<const float4*>(&W[(d + 2) * 4]);
    float4 w3 = *reinterpret_cast<const float4*>(&W[(d + 3) * 4]);
    const float* wp0 = (const float*)&w0;
    const float* wp1 = (const float*)&w1;
    const float* wp2 = (const float*)&w2;
    const float* wp3 = (const float*)&w3;
    #pragma unroll
    for (int j = 0; j < DCONV; j++) {
        int t = l - (DCONV - 1) + j;
        if (t >= 0) {
            float4 xv = *reinterpret_cast<const float4*>(
                &xr[(size_t)t * (2 * DINNER) + d]);
            a0 = fmaf(xv.x, wp0[j], a0);
            a1 = fmaf(xv.y, wp1[j], a1);
            a2 = fmaf(xv.z, wp2[j], a2);
            a3 = fmaf(xv.w, wp3[j], a3);
        }
    }
    float4 o;
    o.x = a0 * sigm(a0);
    o.y = a1 * sigm(a1);
    o.z = a2 * sigm(a2);
    o.w = a3 * sigm(a3);
    *reinterpret_cast<float4*>(&u[(size_t)l * DINNER + d]) = o;
}

// --------------------- chunk-parallel selective scan -----------------------
// scanA: per-chunk transfer function (Aprod, S_local with s0=0). Grid (128, P).
#define TCHUNK 64
__global__ __launch_bounds__(256) void scanA_kernel(
    const float* __restrict__ delta, const float* __restrict__ u,
    const float* __restrict__ xdbl, const float* __restrict__ A_log,
    float* __restrict__ cA, float* __restrict__ cS) {
    const int lane_n = threadIdx.x & 15;
    const int ch_loc = threadIdx.x >> 4;
    const int d = blockIdx.x * 16 + ch_loc;
    const int c = blockIdx.y;
    const float Aneg = -expf(A_log[(size_t)d * DSTATE + lane_n]);
    float s = 0.f, ap = 1.f;

    __shared__ float Bsh[TCHUNK][16];
    __shared__ float dsh[TCHUNK][16];
    __shared__ float ush[TCHUNK][16];

    for (int t0 = c * CLEN; t0 < (c + 1) * CLEN; t0 += TCHUNK) {
        __syncthreads();
        for (int i = threadIdx.x; i < TCHUNK * 16; i += 256) {
            int tt = i >> 4, n = i & 15;
            size_t trow = (size_t)(t0 + tt);
            Bsh[tt][n] = xdbl[trow * XDBL_W + DTRANK + n];
            dsh[tt][n] = delta[trow * DINNER + blockIdx.x * 16 + n];
            ush[tt][n] = u    [trow * DINNER + blockIdx.x * 16 + n];
        }
        __syncthreads();
        #pragma unroll 4
        for (int tt = 0; tt < TCHUNK; ++tt) {
            float dt = dsh[tt][ch_loc];
            float uu = ush[tt][ch_loc];
            float dA = __expf(dt * Aneg);
            float dBu = dt * uu * Bsh[tt][lane_n];
            s = fmaf(dA, s, dBu);
            ap *= dA;
        }
    }
    size_t o = ((size_t)c * DINNER + d) * DSTATE + lane_n;
    cA[o] = ap;
    cS[o] = s;
}

// scanB: compose carries serially over P chunks. One thread per (d,n).
__global__ void scanB_kernel(const float* __restrict__ cA,
                             const float* __restrict__ cS,
                             float* __restrict__ s0) {
    int i = blockIdx.x * blockDim.x + threadIdx.x;   // DINNER*DSTATE = 32768
    float s = 0.f;
    #pragma unroll
    for (int c = 0; c < PCHUNK; c++) {
        size_t o = (size_t)c * DINNER * DSTATE + i;
        s0[o] = s;
        s = fmaf(cA[o], s, cS[o]);
    }
}

// scanC: re-scan each chunk with corrected s0, emit y. Grid (128, P).
__global__ __launch_bounds__(256) void scanC_kernel(
    const float* __restrict__ delta, const float* __restrict__ u,
    const float* __restrict__ xdbl, const float* __restrict__ A_log,
    const float* __restrict__ Dp, const float* __restrict__ s0v,
    float* __restrict__ y) {
    const int lane_n = threadIdx.x & 15;
    const int ch_loc = threadIdx.x >> 4;
    const int d = blockIdx.x * 16 + ch_loc;
    const int c = blockIdx.y;
    const float Aneg = -expf(A_log[(size_t)d * DSTATE + lane_n]);
    const float Dval = Dp[d];
    float s = s0v[((size_t)c * DINNER + d) * DSTATE + lane_n];

    __shared__ float Bsh[TCHUNK][16];
    __shared__ float Csh[TCHUNK][16];
    __shared__ float dsh[TCHUNK][16];
    __shared__ float ush[TCHUNK][16];

    for (int t0 = c * CLEN; t0 < (c + 1) * CLEN; t0 += TCHUNK) {
        __syncthreads();
        for (int i = threadIdx.x; i < TCHUNK * 16; i += 256) {
            int tt = i >> 4, n = i & 15;
            size_t trow = (size_t)(t0 + tt);
            Bsh[tt][n] = xdbl[trow * XDBL_W + DTRANK + n];
            Csh[tt][n] = xdbl[trow * XDBL_W + DTRANK + DSTATE + n];
            dsh[tt][n] = delta[trow * DINNER + blockIdx.x * 16 + n];
            ush[tt][n] = u    [trow * DINNER + blockIdx.x * 16 + n];
        }
        __syncthreads();
        #pragma unroll 4
        for (int tt = 0; tt < TCHUNK; ++tt) {
            float dt = dsh[tt][ch_loc];
            float uu = ush[tt][ch_loc];
            float dA = __expf(dt * Aneg);
            float dBu = dt * uu * Bsh[tt][lane_n];
            s = fmaf(dA, s, dBu);
            float yv = s * Csh[tt][lane_n];
            yv += __shfl_xor_sync(0xffffffffu, yv, 8);
            yv += __shfl_xor_sync(0xffffffffu, yv, 4);
            yv += __shfl_xor_sync(0xffffffffu, yv, 2);
            yv += __shfl_xor_sync(0xffffffffu, yv, 1);
            if (lane_n == 0)
                y[(size_t)(t0 + tt) * DINNER + d] = yv + Dval * uu;
        }
    }
}

// ------------------- silu gate + fp16 hi/lo split (R8 form) ----------------
__global__ void gate_split_kernel(const float* __restrict__ y,
                                  const float* __restrict__ xr,
                                  __half* __restrict__ yh,
                                  __half* __restrict__ yl) {
    int i = blockIdx.x * blockDim.x + threadIdx.x;    // over L*DINNER/4
    int base = i * 4;
    int l = base >> 11;
    int d = base & (DINNER - 1);
    float4 yv = reinterpret_cast<const float4*>(y)[i];
    float4 rv = *reinterpret_cast<const float4*>(
        xr + (size_t)l * (2 * DINNER) + DINNER + d);
    float g0 = yv.x * (rv.x * sigm(rv.x));
    float g1 = yv.y * (rv.y * sigm(rv.y));
    float g2 = yv.z * (rv.z * sigm(rv.z));
    float g3 = yv.w * (rv.w * sigm(rv.w));
    uint2 h, lo;
    split2h(g0, g1, h.x, lo.x);
    split2h(g2, g3, h.y, lo.y);
    reinterpret_cast<uint2*>(yh)[i] = h;
    reinterpret_cast<uint2*>(yl)[i] = lo;
}

// ------------------------------- launcher ----------------------------------
extern "C" void kernel_launch(void* const* d_in, const int* in_sizes, int n_in,
                              void* d_out, int out_size) {
    const int*   tokens    = (const int*)  d_in[0];
    const float* emb_W     = (const float*)d_in[1];
    const float* in_proj_W = (const float*)d_in[2];
    const float* conv_W    = (const float*)d_in[3];
    const float* conv_b    = (const float*)d_in[4];
    const float* xproj_W   = (const float*)d_in[5];
    const float* dt_W      = (const float*)d_in[6];
    const float* dt_b      = (const float*)d_in[7];
    const float* A_log     = (const float*)d_in[8];
    const float* Dp        = (const float*)d_in[9];
    const float* out_W     = (const float*)d_in[10];
    const float* rms_w     = (const float*)d_in[11];
    const float* rms_b     = (const float*)d_in[12];
    const float* normf_w   = (const float*)d_in[13];
    const float* normf_b   = (const float*)d_in[14];
    float* out = (float*)d_out;

    float *px, *pxr, *pu, *pxdbl, *pdelta, *py, *ppart, *pcA, *pcS, *ps0;
    __half *phh, *phl, *pyh, *pyl, *pwi, *pwo, *pembh;
    cudaGetSymbolAddress((void**)&px,     g_x);
    cudaGetSymbolAddress((void**)&pxr,    g_xr);
    cudaGetSymbolAddress((void**)&pu,     g_u);
    cudaGetSymbolAddress((void**)&pxdbl,  g_xdbl);
    cudaGetSymbolAddress((void**)&pdelta, g_delta);
    cudaGetSymbolAddress((void**)&py,     g_y);
    cudaGetSymbolAddress((void**)&ppart,  g_part);
    cudaGetSymbolAddress((void**)&pcA,    g_cA);
    cudaGetSymbolAddress((void**)&pcS,    g_cS);
    cudaGetSymbolAddress((void**)&ps0,    g_s0);
    cudaGetSymbolAddress((void**)&phh,    g_hh);
    cudaGetSymbolAddress((void**)&phl,    g_hl);
    cudaGetSymbolAddress((void**)&pyh,    g_yh);
    cudaGetSymbolAddress((void**)&pyl,    g_yl);
    cudaGetSymbolAddress((void**)&pwi,    g_wi);
    cudaGetSymbolAddress((void**)&pwo,    g_wo);
    cudaGetSymbolAddress((void**)&pembh,  g_embh);

    cudaFuncSetAttribute(gemm_mma4<false>,
        cudaFuncAttributeMaxDynamicSharedMemorySize, SMEM_G);
    cudaFuncSetAttribute(gemm_mma4<true>,
        cudaFuncAttributeMaxDynamicSharedMemorySize, SMEM_G);

    // ---- weight conversions to fp16 (every launch; deterministic) ----
    {
        int n4 = NLAYERS * 2 * DINNER * NEMBD / 4;
        convert_half_kernel<<<(n4 + 255) / 256, 256>>>(in_proj_W, pwi, n4);
        n4 = NLAYERS * NEMBD * DINNER / 4;
        convert_half_kernel<<<(n4 + 255) / 256, 256>>>(out_W, pwo, n4);
        n4 = (int)((size_t)NVOCAB * NEMBD / 4);
        convert_half_kernel<<<(n4 + 255) / 256, 256>>>(emb_W, pembh, n4);
    }

    embed_kernel<<<LSEQ, 256>>>(tokens, emb_W, px);

    for (int i = 0; i < NLAYERS; i++) {
        rmsnorm_out_kernel<0><<<LSEQ, 256>>>(px, rms_w + i * NEMBD,
                                             rms_b + i * NEMBD, phh, phl);

        // in_proj: xr[L,4096] = h @ W^T  (fp16 hi/lo 2-pass)
        {
            const uint16_t* bw = (const uint16_t*)(pwi + (size_t)i * 2 * DINNER * NEMBD);
            dim3 g(LSEQ / 128, 2 * DINNER / 128);
            gemm_mma4<false><<<g, 256, SMEM_G>>>(
                (const uint16_t*)phh, (const uint16_t*)phl, bw,
                2, pxr, 2 * DINNER, NEMBD, 2 * DINNER);
        }

        conv_silu_kernel<<<LSEQ * DINNER / 4 / 256, 256>>>(
            pxr, conv_W + (size_t)i * DINNER * DCONV, conv_b + i * DINNER, pu);

        // x_proj (N=96): split-K fp32
        {
            dim3 grid(1, LSEQ / 128, 8);
            gemm_nt<false, true, false><<<grid, 256>>>(
                pu, xproj_W + (size_t)i * XDBL_W * DINNER, ppart,
                LSEQ, XDBL_W, DINNER, DINNER, DINNER, XDBL_W,
                DINNER / 8, (long long)LSEQ * XDBL_W, nullptr);
            int n = LSEQ * XDBL_W;
            reduce_split_kernel<<<(n + 255) / 256, 256>>>(
                ppart, pxdbl, n, 8, (long long)LSEQ * XDBL_W);
        }

        // dt proj + fused softplus
        {
            dim3 grid(DINNER / 128, LSEQ / 128);
            gemm_nt<false, false, true><<<grid, 256>>>(
                pxdbl, dt_W + (size_t)i * DINNER * DTRANK, pdelta,
                LSEQ, DINNER, DTRANK, XDBL_W, DTRANK, DINNER, 0, 0,
                dt_b + i * DINNER);
        }

        // chunk-parallel scan: transfer fns -> carries -> corrected re-scan
        {
            const float* Al = A_log + (size_t)i * DINNER * DSTATE;
            dim3 ga(DINNER / 16, PCHUNK);
            scanA_kernel<<<ga, 256>>>(pdelta, pu, pxdbl, Al, pcA, pcS);
            scanB_kernel<<<DINNER * DSTATE / 256, 256>>>(pcA, pcS, ps0);
            scanC_kernel<<<ga, 256>>>(pdelta, pu, pxdbl, Al,
                                      Dp + i * DINNER, ps0, py);
        }

        // gate + fp16 split (R8 form)
        gate_split_kernel<<<LSEQ * DINNER / 4 / 256, 256>>>(py, pxr, pyh, pyl);

        // out_proj accumulate: x += y @ out_W^T  (fp16 hi/lo 2-pass)
        {
            const uint16_t* bw = (const uint16_t*)(pwo + (size_t)i * NEMBD * DINNER);
            dim3 g(LSEQ / 128, NEMBD / 128);
            gemm_mma4<true><<<g, 256, SMEM_G>>>(
                (const uint16_t*)pyh, (const uint16_t*)pyl, bw,
                2, px, NEMBD, DINNER, NEMBD);
        }
    }

    // final norm (fp16 out) + tied lm head (fp16 single pass)
    rmsnorm_out_kernel<1><<<LSEQ, 256>>>(px, normf_w, normf_b, phh, nullptr);
    {
        dim3 g(LSEQ / 128, (NVOCAB + 127) / 128);
        const uint16_t* ah = (const uint16_t*)phh;
        const uint16_t* bh = (const uint16_t*)pembh;
        gemm_mma4<false><<<g, 256, SMEM_G>>>(
            ah, ah, bh, 1, out, NVOCAB, NEMBD, NVOCAB);
    }
}

// round 17
// speedup vs baseline: 2.9648x; 1.0068x over previous
#include <cuda_runtime.h>
#include <cuda_bf16.h>
#include <cuda_fp16.h>
#include <math.h>
#include <stdint.h>

// ---------------------------------------------------------------------------
// Mamba forward, L=2048, 4 layers.
// Big GEMMs via mma.sync (HMMA fp16), CTA 128x128, BK=64, 3-stage cp.async,
// 8 warps, 2 CTAs/SM (R8 config, pipe-saturated ~92 TFMA/s).
// Layer GEMMs = fp16 act-hi/lo 2-pass, lm head = 1-pass.
// Scan: chunk-parallel (P=16): scanA chunk transfer fns -> scanB carry
// composition -> scanC re-scan with corrected s0. Gate separate.
// softplus fused into dt GEMM epilogue.
// ---------------------------------------------------------------------------

#define LSEQ    2048
#define NEMBD   1024
#define DINNER  2048
#define DSTATE  16
#define DTRANK  64
#define DCONV   4
#define NVOCAB  50257
#define NLAYERS 4
#define XDBL_W  (DTRANK + 2 * DSTATE)   // 96
#define PCHUNK  16
#define CLEN    (LSEQ / PCHUNK)         // 128

// ----------------------------- scratch (static) ----------------------------
__device__ __align__(16) float g_x    [LSEQ * NEMBD];
__device__ __align__(16) float g_xr   [LSEQ * 2 * DINNER];
__device__ __align__(16) float g_u    [LSEQ * DINNER];
__device__ __align__(16) float g_xdbl [LSEQ * XDBL_W];
__device__ __align__(16) float g_delta[LSEQ * DINNER];
__device__ __align__(16) float g_y    [LSEQ * DINNER];
__device__ __align__(16) float g_part [8 * LSEQ * XDBL_W];
__device__ __align__(16) float g_cA   [PCHUNK * DINNER * DSTATE];
__device__ __align__(16) float g_cS   [PCHUNK * DINNER * DSTATE];
__device__ __align__(16) float g_s0   [PCHUNK * DINNER * DSTATE];

__device__ __align__(16) __half g_hh [LSEQ * NEMBD];    // activations hi
__device__ __align__(16) __half g_hl [LSEQ * NEMBD];    // activations lo
__device__ __align__(16) __half g_yh [LSEQ * DINNER];
__device__ __align__(16) __half g_yl [LSEQ * DINNER];
__device__ __align__(16) __half g_wi [NLAYERS * 2 * DINNER * NEMBD];
__device__ __align__(16) __half g_wo [NLAYERS * NEMBD * DINNER];
__device__ __align__(16) __half g_embh[(size_t)NVOCAB * NEMBD];

// ----------------------------- MMA helpers ---------------------------------
__device__ __forceinline__ void ldm_x4(uint32_t* r, uint32_t a) {
    asm volatile("ldmatrix.sync.aligned.m8n8.x4.shared.b16 {%0,%1,%2,%3}, [%4];"
                 : "=r"(r[0]), "=r"(r[1]), "=r"(r[2]), "=r"(r[3]) : "r"(a));
}
__device__ __forceinline__ void mma_16816(float* c, const uint32_t* a, const uint32_t* b) {
    asm volatile("mma.sync.aligned.m16n8k16.row.col.f32.f16.f16.f32 "
        "{%0,%1,%2,%3}, {%4,%5,%6,%7}, {%8,%9}, {%0,%1,%2,%3};"
        : "+f"(c[0]), "+f"(c[1]), "+f"(c[2]), "+f"(c[3])
        : "r"(a[0]), "r"(a[1]), "r"(a[2]), "r"(a[3]), "r"(b[0]), "r"(b[1]));
}

#define CPASYNC16(dst, src, sz) \
    asm volatile("cp.async.cg.shared.global [%0], [%1], 16, %2;" \
                 :: "r"(dst), "l"(src), "r"(sz))

// ------------- HMMA NT GEMM: C[M,N] (+)= sum_p A_p B^T ---------------------
// (R8 config — benched 2974us; do not grow the COMPUTE body: reg budget 128.)
template <bool ACC>
__global__ __launch_bounds__(256, 2) void gemm_mma4(
    const uint16_t* __restrict__ A0, const uint16_t* __restrict__ A1,
    const uint16_t* __restrict__ B,
    int npass, float* __restrict__ C, int N, int K, int ldc) {
    extern __shared__ __align__(16) uint16_t sm[];
    constexpr int PITCH = 72;
    constexpr int ASTR = 128 * PITCH;
    constexpr int BSTR = 128 * PITCH;

    const int tid = threadIdx.x, lane = tid & 31, wid = tid >> 5;
    const int bm = blockIdx.x * 128, bn = blockIdx.y * 128;
    const int kc64 = K >> 6;
    const int NC = npass * kc64;

    const uint32_t smBase = (uint32_t)__cvta_generic_to_shared(sm);
    const int lrow = tid >> 3, lch = tid & 7;

    const int arow = (lane & 7) + ((lane >> 3) & 1) * 8;
    const int akc  = lane >> 4;
    const int brow = (lane & 7) + ((lane >> 4) << 3);
    const int bkc  = (lane >> 3) & 1;
    const int wm = (wid & 1) * 64;
    const int wn = (wid >> 1) * 32;

    float acc[4][4][4];
    #pragma unroll
    for (int i = 0; i < 4; i++)
        #pragma unroll
        for (int j = 0; j < 4; j++)
            #pragma unroll
            for (int k = 0; k < 4; k++) acc[i][j][k] = 0.f;

#define ISSUE(st, c) do { \
    int _p = (c) / kc64, _k = (c) - _p * kc64; \
    const uint16_t* _Aw = (_p == 0) ? A0 : A1; \
    _Pragma("unroll") \
    for (int _it = 0; _it < 4; _it++) { \
        int _r = lrow + _it * 32; \
        const uint16_t* _ga = _Aw + (size_t)(bm + _r) * K + _k * 64 + lch * 8; \
        uint32_t _da = smBase + 2u * ((st) * ASTR + _r * PITCH + lch * 8); \
        CPASYNC16(_da, _ga, 16); \
    } \
    _Pragma("unroll") \
    for (int _it = 0; _it < 4; _it++) { \
        int _r = lrow + _it * 32; \
        int _gr = bn + _r; \
        const uint16_t* _gb = B + (size_t)((_gr < N) ? _gr : 0) * K + _k * 64 + lch * 8; \
        uint32_t _db = smBase + 2u * (3 * ASTR + (st) * BSTR + _r * PITCH + lch * 8); \
        CPASYNC16(_db, _gb, (_gr < N) ? 16 : 0); \
    } \
  } while (0)

#define COMPUTE(st) do { \
    uint32_t _ab = smBase + 2u * ((st) * ASTR); \
    uint32_t _bb = smBase + 2u * (3 * ASTR + (st) * BSTR); \
    _Pragma("unroll") \
    for (int kk = 0; kk < 4; kk++) { \
        uint32_t af[4][4], bf[2][4]; \
        _Pragma("unroll") \
        for (int mi = 0; mi < 4; mi++) \
            ldm_x4(af[mi], _ab + 2u * ((wm + mi * 16 + arow) * PITCH + (kk * 2 + akc) * 8)); \
        _Pragma("unroll") \
        for (int nb = 0; nb < 2; nb++) \
            ldm_x4(bf[nb], _bb + 2u * ((wn + nb * 16 + brow) * PITCH + (kk * 2 + bkc) * 8)); \
        _Pragma("unroll") \
        for (int mi = 0; mi < 4; mi++) \
            _Pragma("unroll") \
            for (int ni = 0; ni < 4; ni++) \
                mma_16816(acc[mi][ni], af[mi], &bf[ni >> 1][(ni & 1) * 2]); \
    } \
  } while (0)

    ISSUE(0, 0);
    asm volatile("cp.async.commit_group;" ::: "memory");
    ISSUE(1, 1);
    asm volatile("cp.async.commit_group;" ::: "memory");

    for (int c = 0; c < NC; c++) {
        asm volatile("cp.async.wait_group 1;" ::: "memory");
        __syncthreads();
        if (c + 2 < NC) ISSUE((c + 2) % 3, c + 2);
        asm volatile("cp.async.commit_group;" ::: "memory");
        COMPUTE(c % 3);
    }
#undef ISSUE
#undef COMPUTE

    const int gid = lane >> 2, q2 = (lane & 3) * 2;
    #pragma unroll
    for (int mi = 0; mi < 4; mi++) {
        const size_t row0 = (size_t)(bm + wm + mi * 16 + gid);
        const size_t row1 = row0 + 8;
        #pragma unroll
        for (int ni = 0; ni < 4; ni++) {
            const int col = bn + wn + ni * 8 + q2;
            const float* cf = acc[mi][ni];
            if (col < N) {
                if (ACC) { C[row0 * ldc + col] += cf[0]; C[row1 * ldc + col] += cf[2]; }
                else     { C[row0 * ldc + col]  = cf[0]; C[row1 * ldc + col]  = cf[2]; }
            }
            if (col + 1 < N) {
                if (ACC) { C[row0 * ldc + col + 1] += cf[1]; C[row1 * ldc + col + 1] += cf[3]; }
                else     { C[row0 * ldc + col + 1]  = cf[1]; C[row1 * ldc + col + 1]  = cf[3]; }
            }
        }
    }
}

#define SMEM_G (3 * (128 + 128) * 72 * 2)   // 110592 B

// ----------------------------- small helpers -------------------------------
__device__ __forceinline__ float sigm(float x) { return 1.0f / (1.0f + expf(-x)); }
__device__ __forceinline__ uint32_t packh2(float a, float b) {
    return (uint32_t)__half_as_ushort(__float2half_rn(a)) |
           ((uint32_t)__half_as_ushort(__float2half_rn(b)) << 16);
}
__device__ __forceinline__ void split2h(float a, float b, uint32_t& hi, uint32_t& lo) {
    __half ha = __float2half_rn(a), hb = __float2half_rn(b);
    float la = a - __half2float(ha), lb = b - __half2float(hb);
    hi = (uint32_t)__half_as_ushort(ha) | ((uint32_t)__half_as_ushort(hb) << 16);
    lo = packh2(la, lb);
}

// ----------------------------- conversions ---------------------------------
__global__ void convert_half_kernel(const float* __restrict__ src,
                                    __half* __restrict__ dst, int n4) {
    int i = blockIdx.x * blockDim.x + threadIdx.x;
    if (i >= n4) return;
    float4 v = reinterpret_cast<const float4*>(src)[i];
    uint2 o;
    o.x = packh2(v.x, v.y);
    o.y = packh2(v.z, v.w);
    reinterpret_cast<uint2*>(dst)[i] = o;
}

// ----------------------------- embedding gather ----------------------------
__global__ void embed_kernel(const int* __restrict__ tokens,
                             const float* __restrict__ emb,
                             float* __restrict__ x) {
    int l = blockIdx.x;
    int tok = tokens[l];
    const float4* src = reinterpret_cast<const float4*>(emb + (size_t)tok * NEMBD);
    float4* dst = reinterpret_cast<float4*>(x + (size_t)l * NEMBD);
    dst[threadIdx.x] = src[threadIdx.x];
}

// ---------------- rmsnorm (width 1024) with fp16 outputs -------------------
template <int OUT_MODE>
__global__ void rmsnorm_out_kernel(const float* __restrict__ x,
                                   const float* __restrict__ w,
                                   const float* __restrict__ b,
                                   void* __restrict__ out_hi,
                                   void* __restrict__ out_lo) {
    int l = blockIdx.x;
    const float4* xr = reinterpret_cast<const float4*>(x + (size_t)l * NEMBD);
    float4 v = xr[threadIdx.x];
    float ss = v.x * v.x + v.y * v.y + v.z * v.z + v.w * v.w;
    #pragma unroll
    for (int o = 16; o > 0; o >>= 1) ss += __shfl_xor_sync(0xffffffffu, ss, o);
    __shared__ float wsum[8];
    __shared__ float inv_s;
    if ((threadIdx.x & 31) == 0) wsum[threadIdx.x >> 5] = ss;
    __syncthreads();
    if (threadIdx.x == 0) {
        float t = 0.f;
        #pragma unroll
        for (int k = 0; k < 8; k++) t += wsum[k];
        inv_s = rsqrtf(t / (float)NEMBD + 1e-6f);
    }
    __syncthreads();
    float inv = inv_s;
    float4 wv = reinterpret_cast<const float4*>(w)[threadIdx.x];
    float4 bv = reinterpret_cast<const float4*>(b)[threadIdx.x];
    float o0 = v.x * inv * wv.x + bv.x;
    float o1 = v.y * inv * wv.y + bv.y;
    float o2 = v.z * inv * wv.z + bv.z;
    float o3 = v.w * inv * wv.w + bv.w;
    size_t base = (size_t)l * NEMBD / 4 + threadIdx.x;
    if (OUT_MODE == 0) {
        uint2 h, lo;
        split2h(o0, o1, h.x, lo.x);
        split2h(o2, o3, h.y, lo.y);
        reinterpret_cast<uint2*>(out_hi)[base] = h;
        reinterpret_cast<uint2*>(out_lo)[base] = lo;
    } else {
        uint2 o;
        o.x = packh2(o0, o1);
        o.y = packh2(o2, o3);
        reinterpret_cast<uint2*>(out_hi)[base] = o;
    }
}

// ------------------- fp32 tiled NT GEMM (small GEMMs) ----------------------
template <bool ACC, bool SPLIT, bool SOFTP>
__global__ __launch_bounds__(256) void gemm_nt(
    const float* __restrict__ A, const float* __restrict__ B,
    float* __restrict__ C, int M, int N, int K,
    int lda, int ldb, int ldc, int kchunk, long long cstride,
    const float* __restrict__ bias) {
    __shared__ float As[16][128 + 4];
    __shared__ float Bs[16][128 + 4];

    int k_begin = 0, k_end = K;
    if (SPLIT) {
        k_begin = blockIdx.z * kchunk;
        k_end = min(K, k_begin + kchunk);
        C += (long long)blockIdx.z * cstride;
    }
    const int bm = blockIdx.y * 128;
    const int bn = blockIdx.x * 128;
    const int tid = threadIdx.x;
    const int tx = tid & 15;
    const int ty = tid >> 4;

    float acc[8][8];
    #pragma unroll
    for (int i = 0; i < 8; i++)
        #pragma unroll
        for (int j = 0; j < 8; j++) acc[i][j] = 0.f;

    for (int k0 = k_begin; k0 < k_end; k0 += 16) {
        #pragma unroll
        for (int s = 0; s < 2; ++s) {
            int idx = tid + s * 256;
            int row = idx >> 2;
            int k4 = (idx & 3) * 4;
            float4 va = *reinterpret_cast<const float4*>(
                &A[(size_t)(bm + row) * lda + k0 + k4]);
            As[k4 + 0][row] = va.x; As[k4 + 1][row] = va.y;
            As[k4 + 2][row] = va.z; As[k4 + 3][row] = va.w;
            float4 vb;
            if (bn + row < N)
                vb = *reinterpret_cast<const float4*>(
                    &B[(size_t)(bn + row) * ldb + k0 + k4]);
            else
                vb = make_float4(0.f, 0.f, 0.f, 0.f);
            Bs[k4 + 0][row] = vb.x; Bs[k4 + 1][row] = vb.y;
            Bs[k4 + 2][row] = vb.z; Bs[k4 + 3][row] = vb.w;
        }
        __syncthreads();
        #pragma unroll
        for (int kk = 0; kk < 16; ++kk) {
            float a[8], b[8];
            *reinterpret_cast<float4*>(&a[0]) =
                *reinterpret_cast<const float4*>(&As[kk][ty * 4]);
            *reinterpret_cast<float4*>(&a[4]) =
                *reinterpret_cast<const float4*>(&As[kk][64 + ty * 4]);
            *reinterpret_cast<float4*>(&b[0]) =
                *reinterpret_cast<const float4*>(&Bs[kk][tx * 4]);
            *reinterpret_cast<float4*>(&b[4]) =
                *reinterpret_cast<const float4*>(&Bs[kk][64 + tx * 4]);
            #pragma unroll
            for (int i = 0; i < 8; i++)
                #pragma unroll
                for (int j = 0; j < 8; j++)
                    acc[i][j] = fmaf(a[i], b[j], acc[i][j]);
        }
        __syncthreads();
    }

    #pragma unroll
    for (int i = 0; i < 8; i++) {
        int ri = bm + ((i < 4) ? (ty * 4 + i) : (64 + ty * 4 + (i - 4)));
        #pragma unroll
        for (int j = 0; j < 8; j++) {
            int cj = bn + ((j < 4) ? (tx * 4 + j) : (64 + tx * 4 + (j - 4)));
            if (cj < N) {
                size_t off = (size_t)ri * ldc + cj;
                float v = acc[i][j];
                if (SOFTP) {
                    float t = v + bias[cj];
                    v = fmaxf(t, 0.f) + log1pf(expf(-fabsf(t)));
                }
                if (ACC) C[off] += v;
                else     C[off]  = v;
            }
        }
    }
}

__global__ void reduce_split_kernel(const float* __restrict__ part,
                                    float* __restrict__ out,
                                    int n, int nz, long long stride) {
    int i = blockIdx.x * blockDim.x + threadIdx.x;
    if (i < n) {
        float s = 0.f;
        for (int z = 0; z < nz; z++) s += part[(long long)z * stride + i];
        out[i] = s;
    }
}

// --------------- depthwise causal conv + silu (float4) ---------------------
__global__ void conv_silu_kernel(const float* __restrict__ xr,
                                 const float* __restrict__ W,
                                 const float* __restrict__ b,
                                 float* __restrict__ u) {
    int i = blockIdx.x * blockDim.x + threadIdx.x;   // over L*DINNER/4
    int d = (i * 4) & (DINNER - 1);
    int l = (i * 4) >> 11;
    float4 bb = *reinterpret_cast<const float4*>(&b[d]);
    float a0 = bb.x, a1 = bb.y, a2 = bb.z, a3 = bb.w;
    float4 w0 = *reinterpret_cast<const float4*>(&W[(d + 0) * 4]);
    float4 w1 = *reinterpret_cast<const float4*>(&W[(d + 1) * 4]);
    float4 w2 = *reinterpret_cast<const float4*>(&W[(d + 2) * 4]);
    float4 w3 = *reinterpret_cast<const float4*>(&W[(d + 3) * 4]);
    const float* wp0 = (const float*)&w0;
    const float* wp1 = (const float*)&w1;
    const float* wp2 = (const float*)&w2;
    const float* wp3 = (const float*)&w3;
    #pragma unroll
    for (int j = 0; j < DCONV; j++) {
        int t = l - (DCONV - 1) + j;
        if (t >= 0) {
            float4 xv = *reinterpret_cast<const float4*>(
                &xr[(size_t)t * (2 * DINNER) + d]);
            a0 = fmaf(xv.x, wp0[j], a0);
            a1 = fmaf(xv.y, wp1[j], a1);
            a2 = fmaf(xv.z, wp2[j], a2);
            a3 = fmaf(xv.w, wp3[j], a3);
        }
    }
    float4 o;
    o.x = a0 * sigm(a0);
    o.y = a1 * sigm(a1);
    o.z = a2 * sigm(a2);
    o.w = a3 * sigm(a3);
    *reinterpret_cast<float4*>(&u[(size_t)l * DINNER + d]) = o;
}

// --------------------- chunk-parallel selective scan -----------------------
// scanA: per-chunk transfer function (Aprod, S_local with s0=0). Grid (128, P).
#define TCHUNK 64
__global__ __launch_bounds__(256) void scanA_kernel(
    const float* __restrict__ delta, const float* __restrict__ u,
    const float* __restrict__ xdbl, const float* __restrict__ A_log,
    float* __restrict__ cA, float* __restrict__ cS) {
    const int lane_n = threadIdx.x & 15;
    const int ch_loc = threadIdx.x >> 4;
    const int d = blockIdx.x * 16 + ch_loc;
    const int c = blockIdx.y;
    const float Aneg = -expf(A_log[(size_t)d * DSTATE + lane_n]);
    float s = 0.f, ap = 1.f;

    __shared__ float Bsh[TCHUNK][16];
    __shared__ float dsh[TCHUNK][16];
    __shared__ float ush[TCHUNK][16];

    for (int t0 = c * CLEN; t0 < (c + 1) * CLEN; t0 += TCHUNK) {
        __syncthreads();
        for (int i = threadIdx.x; i < TCHUNK * 16; i += 256) {
            int tt = i >> 4, n = i & 15;
            size_t trow = (size_t)(t0 + tt);
            Bsh[tt][n] = xdbl[trow * XDBL_W + DTRANK + n];
            dsh[tt][n] = delta[trow * DINNER + blockIdx.x * 16 + n];
            ush[tt][n] = u    [trow * DINNER + blockIdx.x * 16 + n];
        }
        __syncthreads();
        #pragma unroll 4
        for (int tt = 0; tt < TCHUNK; ++tt) {
            float dt = dsh[tt][ch_loc];
            float uu = ush[tt][ch_loc];
            float dA = __expf(dt * Aneg);
            float dBu = dt * uu * Bsh[tt][lane_n];
            s = fmaf(dA, s, dBu);
            ap *= dA;
        }
    }
    size_t o = ((size_t)c * DINNER + d) * DSTATE + lane_n;
    cA[o] = ap;
    cS[o] = s;
}

// scanB: compose carries serially over P chunks. One thread per (d,n).
__global__ void scanB_kernel(const float* __restrict__ cA,
                             const float* __restrict__ cS,
                             float* __restrict__ s0) {
    int i = blockIdx.x * blockDim.x + threadIdx.x;   // DINNER*DSTATE = 32768
    float s = 0.f;
    #pragma unroll
    for (int c = 0; c < PCHUNK; c++) {
        size_t o = (size_t)c * DINNER * DSTATE + i;
        s0[o] = s;
        s = fmaf(cA[o], s, cS[o]);
    }
}

// scanC: re-scan each chunk with corrected s0, emit y. Grid (128, P).
__global__ __launch_bounds__(256) void scanC_kernel(
    const float* __restrict__ delta, const float* __restrict__ u,
    const float* __restrict__ xdbl, const float* __restrict__ A_log,
    const float* __restrict__ Dp, const float* __restrict__ s0v,
    float* __restrict__ y) {
    const int lane_n = threadIdx.x & 15;
    const int ch_loc = threadIdx.x >> 4;
    const int d = blockIdx.x * 16 + ch_loc;
    const int c = blockIdx.y;
    const float Aneg = -expf(A_log[(size_t)d * DSTATE + lane_n]);
    const float Dval = Dp[d];
    float s = s0v[((size_t)c * DINNER + d) * DSTATE + lane_n];

    __shared__ float Bsh[TCHUNK][16];
    __shared__ float Csh[TCHUNK][16];
    __shared__ float dsh[TCHUNK][16];
    __shared__ float ush[TCHUNK][16];

    for (int t0 = c * CLEN; t0 < (c + 1) * CLEN; t0 += TCHUNK) {
        __syncthreads();
        for (int i = threadIdx.x; i < TCHUNK * 16; i += 256) {
            int tt = i >> 4, n = i & 15;
            size_t trow = (size_t)(t0 + tt);
            Bsh[tt][n] = xdbl[trow * XDBL_W + DTRANK + n];
            Csh[tt][n] = xdbl[trow * XDBL_W + DTRANK + DSTATE + n];
            dsh[tt][n] = delta[trow * DINNER + blockIdx.x * 16 + n];
            ush[tt][n] = u    [trow * DINNER + blockIdx.x * 16 + n];
        }
        __syncthreads();
        #pragma unroll 4
        for (int tt = 0; tt < TCHUNK; ++tt) {
            float dt = dsh[tt][ch_loc];
            float uu = ush[tt][ch_loc];
            float dA = __expf(dt * Aneg);
            float dBu = dt * uu * Bsh[tt][lane_n];
            s = fmaf(dA, s, dBu);
            float yv = s * Csh[tt][lane_n];
            yv += __shfl_xor_sync(0xffffffffu, yv, 8);
            yv += __shfl_xor_sync(0xffffffffu, yv, 4);
            yv += __shfl_xor_sync(0xffffffffu, yv, 2);
            yv += __shfl_xor_sync(0xffffffffu, yv, 1);
            if (lane_n == 0)
                y[(size_t)(t0 + tt) * DINNER + d] = yv + Dval * uu;
        }
    }
}

// ------------------- silu gate + fp16 hi/lo split (R8 form) ----------------
__global__ void gate_split_kernel(const float* __restrict__ y,
                                  const float* __restrict__ xr,
                                  __half* __restrict__ yh,
                                  __half* __restrict__ yl) {
    int i = blockIdx.x * blockDim.x + threadIdx.x;    // over L*DINNER/4
    int base = i * 4;
    int l = base >> 11;
    int d = base & (DINNER - 1);
    float4 yv = reinterpret_cast<const float4*>(y)[i];
    float4 rv = *reinterpret_cast<const float4*>(
        xr + (size_t)l * (2 * DINNER) + DINNER + d);
    float g0 = yv.x * (rv.x * sigm(rv.x));
    float g1 = yv.y * (rv.y * sigm(rv.y));
    float g2 = yv.z * (rv.z * sigm(rv.z));
    float g3 = yv.w * (rv.w * sigm(rv.w));
    uint2 h, lo;
    split2h(g0, g1, h.x, lo.x);
    split2h(g2, g3, h.y, lo.y);
    reinterpret_cast<uint2*>(yh)[i] = h;
    reinterpret_cast<uint2*>(yl)[i] = lo;
}

// ------------------------------- launcher ----------------------------------
extern "C" void kernel_launch(void* const* d_in, const int* in_sizes, int n_in,
                              void* d_out, int out_size) {
    const int*   tokens    = (const int*)  d_in[0];
    const float* emb_W     = (const float*)d_in[1];
    const float* in_proj_W = (const float*)d_in[2];
    const float* conv_W    = (const float*)d_in[3];
    const float* conv_b    = (const float*)d_in[4];
    const float* xproj_W   = (const float*)d_in[5];
    const float* dt_W      = (const float*)d_in[6];
    const float* dt_b      = (const float*)d_in[7];
    const float* A_log     = (const float*)d_in[8];
    const float* Dp        = (const float*)d_in[9];
    const float* out_W     = (const float*)d_in[10];
    const float* rms_w     = (const float*)d_in[11];
    const float* rms_b     = (const float*)d_in[12];
    const float* normf_w   = (const float*)d_in[13];
    const float* normf_b   = (const float*)d_in[14];
    float* out = (float*)d_out;

    float *px, *pxr, *pu, *pxdbl, *pdelta, *py, *ppart, *pcA, *pcS, *ps0;
    __half *phh, *phl, *pyh, *pyl, *pwi, *pwo, *pembh;
    cudaGetSymbolAddress((void**)&px,     g_x);
    cudaGetSymbolAddress((void**)&pxr,    g_xr);
    cudaGetSymbolAddress((void**)&pu,     g_u);
    cudaGetSymbolAddress((void**)&pxdbl,  g_xdbl);
    cudaGetSymbolAddress((void**)&pdelta, g_delta);
    cudaGetSymbolAddress((void**)&py,     g_y);
    cudaGetSymbolAddress((void**)&ppart,  g_part);
    cudaGetSymbolAddress((void**)&pcA,    g_cA);
    cudaGetSymbolAddress((void**)&pcS,    g_cS);
    cudaGetSymbolAddress((void**)&ps0,    g_s0);
    cudaGetSymbolAddress((void**)&phh,    g_hh);
    cudaGetSymbolAddress((void**)&phl,    g_hl);
    cudaGetSymbolAddress((void**)&pyh,    g_yh);
    cudaGetSymbolAddress((void**)&pyl,    g_yl);
    cudaGetSymbolAddress((void**)&pwi,    g_wi);
    cudaGetSymbolAddress((void**)&pwo,    g_wo);
    cudaGetSymbolAddress((void**)&pembh,  g_embh);

    cudaFuncSetAttribute(gemm_mma4<false>,
        cudaFuncAttributeMaxDynamicSharedMemorySize, SMEM_G);
    cudaFuncSetAttribute(gemm_mma4<true>,
        cudaFuncAttributeMaxDynamicSharedMemorySize, SMEM_G);

    // ---- weight conversions to fp16 (every launch; deterministic) ----
    {
        int n4 = NLAYERS * 2 * DINNER * NEMBD / 4;
        convert_half_kernel<<<(n4 + 255) / 256, 256>>>(in_proj_W, pwi, n4);
        n4 = NLAYERS * NEMBD * DINNER / 4;
        convert_half_kernel<<<(n4 + 255) / 256, 256>>>(out_W, pwo, n4);
        n4 = (int)((size_t)NVOCAB * NEMBD / 4);
        convert_half_kernel<<<(n4 + 255) / 256, 256>>>(emb_W, pembh, n4);
    }

    embed_kernel<<<LSEQ, 256>>>(tokens, emb_W, px);

    for (int i = 0; i < NLAYERS; i++) {
        rmsnorm_out_kernel<0><<<LSEQ, 256>>>(px, rms_w + i * NEMBD,
                                             rms_b + i * NEMBD, phh, phl);

        // in_proj: xr[L,4096] = h @ W^T  (fp16 hi/lo 2-pass)
        {
            const uint16_t* bw = (const uint16_t*)(pwi + (size_t)i * 2 * DINNER * NEMBD);
            dim3 g(LSEQ / 128, 2 * DINNER / 128);
            gemm_mma4<false><<<g, 256, SMEM_G>>>(
                (const uint16_t*)phh, (const uint16_t*)phl, bw,
                2, pxr, 2 * DINNER, NEMBD, 2 * DINNER);
        }

        conv_silu_kernel<<<LSEQ * DINNER / 4 / 256, 256>>>(
            pxr, conv_W + (size_t)i * DINNER * DCONV, conv_b + i * DINNER, pu);

        // x_proj (N=96): split-K fp32
        {
            dim3 grid(1, LSEQ / 128, 8);
            gemm_nt<false, true, false><<<grid, 256>>>(
                pu, xproj_W + (size_t)i * XDBL_W * DINNER, ppart,
                LSEQ, XDBL_W, DINNER, DINNER, DINNER, XDBL_W,
                DINNER / 8, (long long)LSEQ * XDBL_W, nullptr);
            int n = LSEQ * XDBL_W;
            reduce_split_kernel<<<(n + 255) / 256, 256>>>(
                ppart, pxdbl, n, 8, (long long)LSEQ * XDBL_W);
        }

        // dt proj + fused softplus
        {
            dim3 grid(DINNER / 128, LSEQ / 128);
            gemm_nt<false, false, true><<<grid, 256>>>(
                pxdbl, dt_W + (size_t)i * DINNER * DTRANK, pdelta,
                LSEQ, DINNER, DTRANK, XDBL_W, DTRANK, DINNER, 0, 0,
                dt_b + i * DINNER);
        }

        // chunk-parallel scan: transfer fns -> carries -> corrected re-scan
        {
            const float* Al = A_log + (size_t)i * DINNER * DSTATE;
            dim3 ga(DINNER / 16, PCHUNK);
            scanA_kernel<<<ga, 256>>>(pdelta, pu, pxdbl, Al, pcA, pcS);
            scanB_kernel<<<DINNER * DSTATE / 256, 256>>>(pcA, pcS, ps0);
            scanC_kernel<<<ga, 256>>>(pdelta, pu, pxdbl, Al,
                                      Dp + i * DINNER, ps0, py);
        }

        // gate + fp16 split (R8 form)
        gate_split_kernel<<<LSEQ * DINNER / 4 / 256, 256>>>(py, pxr, pyh, pyl);

        // out_proj accumulate: x += y @ out_W^T  (fp16 hi/lo 2-pass)
        {
            const uint16_t* bw = (const uint16_t*)(pwo + (size_t)i * NEMBD * DINNER);
            dim3 g(LSEQ / 128, NEMBD / 128);
            gemm_mma4<true><<<g, 256, SMEM_G>>>(
                (const uint16_t*)pyh, (const uint16_t*)pyl, bw,
                2, px, NEMBD, DINNER, NEMBD);
        }
    }

    // final norm (fp16 out) + tied lm head (fp16 single pass)
    rmsnorm_out_kernel<1><<<LSEQ, 256>>>(px, normf_w, normf_b, phh, nullptr);
    {
        dim3 g(LSEQ / 128, (NVOCAB + 127) / 128);
        const uint16_t* ah = (const uint16_t*)phh;
        const uint16_t* bh = (const uint16_t*)pembh;
        gemm_mma4<false><<<g, 256, SMEM_G>>>(
            ah, ah, bh, 1, out, NVOCAB, NEMBD, NVOCAB);
    }
}